// round 2
// baseline (speedup 1.0000x reference)
#include <cuda_runtime.h>
#include <math.h>

// ---------------------------------------------------------------------------
// FullTimeAtt: B=2, C=64, F=256, T=1024, R=8, SUP=8, Fatt=32, D=256, H=8, hd=32
// All-fp32 baseline. Scratch in __device__ globals (no allocations).
// ---------------------------------------------------------------------------

__device__ float g_attm[2 * 768];          // shift|scale|gate (attention adaLN)
__device__ float g_mlpm[2 * 192];          // sh2|sc2|g2 (mlp adaLN)
__device__ float g_cos[1024 * 16];
__device__ float g_sin[1024 * 16];
__device__ float g_xf  [2 * 256 * 1024];   // [b][d][t] after sup-GLU
__device__ float g_xt  [2 * 1024 * 256];   // [b][t][d] after LN+modulate
__device__ float g_qkv [2 * 1024 * 768];   // [b][t][3*256]
__device__ float g_attn[2 * 1024 * 256];   // [b][t][d] attention output
__device__ float g_o   [2 * 1024 * 256];   // [b][t][d] gated projected
__device__ float g_ln2 [2 * 256 * 1024];   // [b][d][t] after up_norm

// ---------------------------------------------------------------------------
// K0: csil = silu(c); adaLN matvecs (2x768 and 2x192, each dot length 512)
// ---------------------------------------------------------------------------
__global__ void k_ada(const float* __restrict__ c,
                      const float* __restrict__ aw, const float* __restrict__ ab,
                      const float* __restrict__ mw, const float* __restrict__ mb) {
    __shared__ float cs[1024];
    int tid = threadIdx.x;  // 256 threads
    for (int i = tid; i < 1024; i += 256) {
        float v = c[i];
        cs[i] = v / (1.f + expf(-v));
    }
    __syncthreads();
    for (int i = tid; i < 2 * 768; i += 256) {
        int b = i / 768, o = i - b * 768;
        const float* w = aw + o * 512;
        const float* xx = cs + b * 512;
        float acc = ab[o];
        for (int k = 0; k < 512; k++) acc = fmaf(w[k], xx[k], acc);
        g_attm[i] = acc;
    }
    for (int i = tid; i < 2 * 192; i += 256) {
        int b = i / 192, o = i - b * 192;
        const float* w = mw + o * 512;
        const float* xx = cs + b * 512;
        float acc = mb[o];
        for (int k = 0; k < 512; k++) acc = fmaf(w[k], xx[k], acc);
        g_mlpm[i] = acc;
    }
}

// ---------------------------------------------------------------------------
// K0b: RoPE tables cos/sin[t][j], j = pair index 0..15, ang = t * 10000^(-2j/32)
// ---------------------------------------------------------------------------
__global__ void k_ropetab() {
    int idx = blockIdx.x * 256 + threadIdx.x;  // 16384
    int t = idx >> 4, j = idx & 15;
    float inv = (float)(1.0 / pow(10000.0, (double)(2 * j) / 32.0));
    float ang = (float)t * inv;
    float s, cc;
    sincosf(ang, &s, &cc);
    g_cos[idx] = cc;
    g_sin[idx] = s;
}

// ---------------------------------------------------------------------------
// K1: LN over C (per b,f,t) + pixel-unshuffle + sup 16x512 matvec + GLU
// block: (ttile, fa, b), 128 threads (one t each). Two passes over 512 inputs.
// Output g_xf[b][d][t], d = s*32 + fa.
// ---------------------------------------------------------------------------
__global__ void k_sup(const float* __restrict__ x,
                      const float* __restrict__ sup_w,
                      const float* __restrict__ sup_b) {
    __shared__ float wt[512 * 16];   // transposed: wt[cr*16+o] = sup_w[o][cr]
    __shared__ float bs[16];
    int tid = threadIdx.x;
    int b = blockIdx.z, fa = blockIdx.y;
    int t = blockIdx.x * 128 + tid;
    for (int i = tid; i < 512 * 16; i += 128) {
        int o = i >> 9, cr = i & 511;
        wt[cr * 16 + o] = sup_w[i];
    }
    if (tid < 16) bs[tid] = sup_b[tid];
    __syncthreads();

    const float* xb = x + ((size_t)(b * 64) * 256 + fa * 8) * 1024 + t;

    float s1[8], s2[8];
#pragma unroll
    for (int r = 0; r < 8; r++) { s1[r] = 0.f; s2[r] = 0.f; }
    for (int cch = 0; cch < 64; cch++) {
#pragma unroll
        for (int r = 0; r < 8; r++) {
            float v = xb[(size_t)(cch * 256 + r) * 1024];
            s1[r] += v;
            s2[r] = fmaf(v, v, s2[r]);
        }
    }
    float mu[8], rs[8];
#pragma unroll
    for (int r = 0; r < 8; r++) {
        mu[r] = s1[r] * (1.f / 64.f);
        float var = s2[r] * (1.f / 64.f) - mu[r] * mu[r];
        rs[r] = rsqrtf(var + 1e-6f);
    }

    float acc[16];
#pragma unroll
    for (int o = 0; o < 16; o++) acc[o] = 0.f;
    for (int cch = 0; cch < 64; cch++) {
#pragma unroll
        for (int r = 0; r < 8; r++) {
            float xn = (xb[(size_t)(cch * 256 + r) * 1024] - mu[r]) * rs[r];
            const float4* w4 = (const float4*)(wt + (cch * 8 + r) * 16);
            float wv[16];
            *(float4*)&wv[0]  = w4[0];
            *(float4*)&wv[4]  = w4[1];
            *(float4*)&wv[8]  = w4[2];
            *(float4*)&wv[12] = w4[3];
#pragma unroll
            for (int o = 0; o < 16; o++) acc[o] = fmaf(wv[o], xn, acc[o]);
        }
    }
#pragma unroll
    for (int s = 0; s < 8; s++) {
        float ya = acc[s] + bs[s];
        float yb = acc[s + 8] + bs[s + 8];
        float outv = ya * (yb / (1.f + __expf(-yb)));
        g_xf[((size_t)(b * 256) + (s * 32 + fa)) * 1024 + t] = outv;
    }
}

// ---------------------------------------------------------------------------
// K2: LN over D=256 (per b,t) + modulate; [b][d][t] -> [b][t][d]
// ---------------------------------------------------------------------------
__global__ void k_ln_mod() {
    __shared__ float shs[256], scs[256];
    int tid = threadIdx.x;  // 128
    int b = blockIdx.y;
    int t = blockIdx.x * 128 + tid;
    for (int i = tid; i < 256; i += 128) {
        shs[i] = g_attm[b * 768 + i];
        scs[i] = 1.f + g_attm[b * 768 + 256 + i];
    }
    __syncthreads();
    const float* src = g_xf + (size_t)b * 256 * 1024 + t;
    float s1 = 0.f, s2 = 0.f;
    for (int d = 0; d < 256; d++) {
        float v = src[(size_t)d * 1024];
        s1 += v;
        s2 = fmaf(v, v, s2);
    }
    float mu = s1 * (1.f / 256.f);
    float rs = rsqrtf(s2 * (1.f / 256.f) - mu * mu + 1e-6f);
    float* dst = g_xt + ((size_t)(b * 1024) + t) * 256;
    for (int d = 0; d < 256; d += 4) {
        float4 o;
        o.x = (src[(size_t)(d + 0) * 1024] - mu) * rs * scs[d + 0] + shs[d + 0];
        o.y = (src[(size_t)(d + 1) * 1024] - mu) * rs * scs[d + 1] + shs[d + 1];
        o.z = (src[(size_t)(d + 2) * 1024] - mu) * rs * scs[d + 2] + shs[d + 2];
        o.w = (src[(size_t)(d + 3) * 1024] - mu) * rs * scs[d + 3] + shs[d + 3];
        *(float4*)(dst + d) = o;
    }
}

// ---------------------------------------------------------------------------
// K3/K5: NT GEMM  C[M][N] = A[M][K] @ W[N][K]^T + bias (optionally * gate)
// 64x64 tile, BK=16, 256 threads, 4x4 micro-tile. M=2048 rows.
// gate != nullptr: C = gate[(row>>10)*768 + col] * (acc + bias)
// ---------------------------------------------------------------------------
__global__ void k_gemm64(const float* __restrict__ A, const float* __restrict__ W,
                         const float* __restrict__ bias, float* __restrict__ C,
                         int N, int K, const float* __restrict__ gate) {
    __shared__ float As[64][17];
    __shared__ float Ws[64][17];
    int tid = threadIdx.x;
    int row0 = blockIdx.y * 64, col0 = blockIdx.x * 64;
    int ty = tid >> 4, tx = tid & 15;
    int lr = tid >> 2, lk = (tid & 3) * 4;
    float acc[4][4];
#pragma unroll
    for (int i = 0; i < 4; i++)
#pragma unroll
        for (int j = 0; j < 4; j++) acc[i][j] = 0.f;

    for (int k0 = 0; k0 < K; k0 += 16) {
        float4 av = *(const float4*)(A + (size_t)(row0 + lr) * K + k0 + lk);
        float4 wv = *(const float4*)(W + (size_t)(col0 + lr) * K + k0 + lk);
        __syncthreads();
        As[lr][lk + 0] = av.x; As[lr][lk + 1] = av.y; As[lr][lk + 2] = av.z; As[lr][lk + 3] = av.w;
        Ws[lr][lk + 0] = wv.x; Ws[lr][lk + 1] = wv.y; Ws[lr][lk + 2] = wv.z; Ws[lr][lk + 3] = wv.w;
        __syncthreads();
#pragma unroll
        for (int kk = 0; kk < 16; kk++) {
            float a[4], bb[4];
#pragma unroll
            for (int i = 0; i < 4; i++) a[i] = As[ty * 4 + i][kk];
#pragma unroll
            for (int j = 0; j < 4; j++) bb[j] = Ws[tx * 4 + j][kk];
#pragma unroll
            for (int i = 0; i < 4; i++)
#pragma unroll
                for (int j = 0; j < 4; j++) acc[i][j] = fmaf(a[i], bb[j], acc[i][j]);
        }
    }
#pragma unroll
    for (int i = 0; i < 4; i++) {
        int r = row0 + ty * 4 + i;
#pragma unroll
        for (int j = 0; j < 4; j++) {
            int cc = col0 + tx * 4 + j;
            float v = acc[i][j] + bias[cc];
            if (gate) v *= gate[(r >> 10) * 768 + cc];
            C[(size_t)r * N + cc] = v;
        }
    }
}

// ---------------------------------------------------------------------------
// K3b: RoPE in place on q and k parts of g_qkv
// ---------------------------------------------------------------------------
__global__ void k_rope() {
    int idx = blockIdx.x * 256 + threadIdx.x;  // 262144
    int row = idx >> 7;
    int hj = idx & 127;
    int h = hj >> 4, j = hj & 15;
    int t = row & 1023;
    float cth = g_cos[t * 16 + j], sth = g_sin[t * 16 + j];
    float* p = g_qkv + (size_t)row * 768 + h * 32 + 2 * j;
    float a = p[0], bb = p[1];
    p[0] = a * cth - bb * sth;
    p[1] = a * sth + bb * cth;
    a = p[256]; bb = p[257];
    p[256] = a * cth - bb * sth;
    p[257] = a * sth + bb * cth;
}

// ---------------------------------------------------------------------------
// K4: attention. block (qtile, h, b), 128 threads = 128 q rows.
// KV tiles of 32, online softmax, acc in registers.
// ---------------------------------------------------------------------------
__global__ void k_attn() {
    __shared__ float ks[32][32];
    __shared__ float vs[32][32];
    __shared__ float sc[128][33];
    int tid = threadIdx.x;
    int b = blockIdx.z, h = blockIdx.y;
    int t = blockIdx.x * 128 + tid;
    const float* qp = g_qkv + ((size_t)(b * 1024) + t) * 768 + h * 32;
    float q[32];
#pragma unroll
    for (int d = 0; d < 32; d += 4) {
        float4 v = *(const float4*)(qp + d);
        q[d] = v.x; q[d + 1] = v.y; q[d + 2] = v.z; q[d + 3] = v.w;
    }
    float m = -1e30f, l = 0.f;
    float acc[32];
#pragma unroll
    for (int d = 0; d < 32; d++) acc[d] = 0.f;
    const float scale = 0.17677669529663689f;  // 32^-0.5

    for (int st0 = 0; st0 < 1024; st0 += 32) {
        __syncthreads();
        for (int i = tid; i < 256; i += 128) {
            int rr = i >> 3, c4 = (i & 7) * 4;
            const float* kb = g_qkv + ((size_t)(b * 1024) + st0 + rr) * 768 + 256 + h * 32 + c4;
            *(float4*)(&ks[rr][c4]) = *(const float4*)kb;
            *(float4*)(&vs[rr][c4]) = *(const float4*)(kb + 256);
        }
        __syncthreads();
        float tmax = -1e30f;
        for (int s = 0; s < 32; s++) {
            float dot = 0.f;
#pragma unroll
            for (int d = 0; d < 32; d++) dot = fmaf(q[d], ks[s][d], dot);
            dot *= scale;
            sc[tid][s] = dot;
            tmax = fmaxf(tmax, dot);
        }
        float mn = fmaxf(m, tmax);
        float corr = __expf(m - mn);
        l *= corr;
#pragma unroll
        for (int d = 0; d < 32; d++) acc[d] *= corr;
        for (int s = 0; s < 32; s++) {
            float p = __expf(sc[tid][s] - mn);
            l += p;
#pragma unroll
            for (int d = 0; d < 32; d++) acc[d] = fmaf(p, vs[s][d], acc[d]);
        }
        m = mn;
    }
    float invl = 1.f / l;
    float* op = g_attn + ((size_t)(b * 1024) + t) * 256 + h * 32;
#pragma unroll
    for (int d = 0; d < 32; d += 4) {
        float4 o;
        o.x = acc[d] * invl; o.y = acc[d + 1] * invl;
        o.z = acc[d + 2] * invl; o.w = acc[d + 3] * invl;
        *(float4*)(op + d) = o;
    }
}

// ---------------------------------------------------------------------------
// K5b: up_norm — LN over D of gated output; [b][t][d] -> [b][d][t]
// ---------------------------------------------------------------------------
__global__ void k_upnorm() {
    int tid = threadIdx.x;  // 128
    int b = blockIdx.y;
    int t = blockIdx.x * 128 + tid;
    const float4* src = (const float4*)(g_o + ((size_t)(b * 1024) + t) * 256);
    float s1 = 0.f, s2 = 0.f;
    for (int i = 0; i < 64; i++) {
        float4 v = src[i];
        s1 += v.x + v.y + v.z + v.w;
        s2 += v.x * v.x + v.y * v.y + v.z * v.z + v.w * v.w;
    }
    float mu = s1 * (1.f / 256.f);
    float rs = rsqrtf(s2 * (1.f / 256.f) - mu * mu + 1e-6f);
    float* dst = g_ln2 + (size_t)b * 256 * 1024 + t;
    for (int i = 0; i < 64; i++) {
        float4 v = src[i];
        dst[(size_t)(4 * i + 0) * 1024] = (v.x - mu) * rs;
        dst[(size_t)(4 * i + 1) * 1024] = (v.y - mu) * rs;
        dst[(size_t)(4 * i + 2) * 1024] = (v.z - mu) * rs;
        dst[(size_t)(4 * i + 3) * 1024] = (v.w - mu) * rs;
    }
}

// ---------------------------------------------------------------------------
// K6: recov conv(3,1) along Fatt + pixel-shuffle + residual -> out (= x_mid)
// block (ttile, fa, b), 128 threads. dyn smem: 512*24 w + 512 b = 51200 B
// ---------------------------------------------------------------------------
__global__ void k_recov(const float* __restrict__ x,
                        const float* __restrict__ rw,
                        const float* __restrict__ rb,
                        float* __restrict__ outp) {
    extern __shared__ float sm6[];
    float* ws = sm6;           // [512][24]
    float* bbs = sm6 + 512 * 24;
    int tid = threadIdx.x;
    int b = blockIdx.z, fa = blockIdx.y;
    int t = blockIdx.x * 128 + tid;
    for (int i = tid; i < 3072; i += 128) ((float4*)ws)[i] = ((const float4*)rw)[i];
    for (int i = tid; i < 512; i += 128) bbs[i] = rb[i];
    __syncthreads();

    float xv[24];
#pragma unroll
    for (int i = 0; i < 8; i++) {
#pragma unroll
        for (int kh = 0; kh < 3; kh++) {
            int fs = fa + kh - 1;
            xv[i * 3 + kh] = (fs >= 0 && fs < 32)
                ? g_ln2[((size_t)(b * 256) + i * 32 + fs) * 1024 + t] : 0.f;
        }
    }
    for (int o = 0; o < 512; o++) {
        const float4* w4 = (const float4*)(ws + o * 24);
        float a0 = bbs[o], a1 = 0.f, a2 = 0.f;
        float4 w;
        w = w4[0]; a0 += w.x * xv[0]  + w.y * xv[1]  + w.z * xv[2]  + w.w * xv[3];
        w = w4[1]; a1 += w.x * xv[4]  + w.y * xv[5]  + w.z * xv[6]  + w.w * xv[7];
        w = w4[2]; a2 += w.x * xv[8]  + w.y * xv[9]  + w.z * xv[10] + w.w * xv[11];
        w = w4[3]; a0 += w.x * xv[12] + w.y * xv[13] + w.z * xv[14] + w.w * xv[15];
        w = w4[4]; a1 += w.x * xv[16] + w.y * xv[17] + w.z * xv[18] + w.w * xv[19];
        w = w4[5]; a2 += w.x * xv[20] + w.y * xv[21] + w.z * xv[22] + w.w * xv[23];
        float accv = a0 + a1 + a2;
        int cch = o >> 3, r = o & 7;
        size_t idx = ((size_t)(b * 64 + cch) * 256 + fa * 8 + r) * 1024 + t;
        outp[idx] = x[idx] + accv;
    }
}

// ---------------------------------------------------------------------------
// K7: gated MLP, in place on out (x_mid). block (ttile, fgroup, b), 128 thr,
// loops 8 f values reusing smem weights. dyn smem = 100352 B.
// ---------------------------------------------------------------------------
__global__ void __launch_bounds__(128)
k_mlp(float* __restrict__ xio,
      const float* __restrict__ fc1w, const float* __restrict__ fc1b,
      const float* __restrict__ fc2w, const float* __restrict__ fc2b) {
    extern __shared__ float sm7[];
    float* w1  = sm7;                   // [256][64]
    float* w2t = sm7 + 16384;           // [128][64] transposed fc2
    float* b1  = sm7 + 16384 + 8192;    // 256
    float* b2  = b1 + 256;              // 64
    float* sh2 = b2 + 64;               // 64
    float* sc2 = sh2 + 64;              // 64
    float* gg2 = sc2 + 64;              // 64
    int tid = threadIdx.x;
    int b = blockIdx.z, fg = blockIdx.y;
    int t = blockIdx.x * 128 + tid;
    for (int i = tid; i < 4096; i += 128) ((float4*)w1)[i] = ((const float4*)fc1w)[i];
    for (int i = tid; i < 8192; i += 128) {
        int c2 = i >> 7, o = i & 127;
        w2t[o * 64 + c2] = fc2w[i];
    }
    for (int i = tid; i < 256; i += 128) b1[i] = fc1b[i];
    if (tid < 64) {
        b2[tid]  = fc2b[tid];
        sh2[tid] = g_mlpm[b * 192 + tid];
        sc2[tid] = g_mlpm[b * 192 + 64 + tid];
        gg2[tid] = g_mlpm[b * 192 + 128 + tid];
    }
    __syncthreads();

    for (int fi = 0; fi < 8; fi++) {
        int f = fg * 8 + fi;
        float* xp = xio + ((size_t)(b * 64) * 256 + f) * 1024 + t;

        float mm[64];
        float s1 = 0.f, s2v = 0.f;
#pragma unroll
        for (int cch = 0; cch < 64; cch++) {
            float v = xp[(size_t)cch * 262144];
            mm[cch] = v;
            s1 += v;
            s2v = fmaf(v, v, s2v);
        }
        float mu = s1 * (1.f / 64.f);
        float rs = rsqrtf(s2v * (1.f / 64.f) - mu * mu + 1e-6f);
#pragma unroll
        for (int cch = 0; cch < 64; cch++)
            mm[cch] = (mm[cch] - mu) * rs * (1.f + sc2[cch]) + sh2[cch];

        float outacc[64];
#pragma unroll
        for (int cch = 0; cch < 64; cch++) outacc[cch] = 0.f;

        for (int o = 0; o < 128; o++) {
            const float4* wa = (const float4*)(w1 + o * 64);
            const float4* wb = (const float4*)(w1 + (o + 128) * 64);
            float u0 = 0.f, u1 = 0.f, gq0 = 0.f, gq1 = 0.f;
#pragma unroll
            for (int qq = 0; qq < 16; qq += 2) {
                float4 a0 = wa[qq], a1 = wa[qq + 1];
                float4 c0 = wb[qq], c1 = wb[qq + 1];
                u0  += a0.x * mm[qq*4+0] + a0.y * mm[qq*4+1] + a0.z * mm[qq*4+2] + a0.w * mm[qq*4+3];
                u1  += a1.x * mm[qq*4+4] + a1.y * mm[qq*4+5] + a1.z * mm[qq*4+6] + a1.w * mm[qq*4+7];
                gq0 += c0.x * mm[qq*4+0] + c0.y * mm[qq*4+1] + c0.z * mm[qq*4+2] + c0.w * mm[qq*4+3];
                gq1 += c1.x * mm[qq*4+4] + c1.y * mm[qq*4+5] + c1.z * mm[qq*4+6] + c1.w * mm[qq*4+7];
            }
            float u = u0 + u1 + b1[o];
            float g = gq0 + gq1 + b1[o + 128];
            float hh = u * (g / (1.f + __expf(-g)));
            const float4* wc = (const float4*)(w2t + o * 64);
#pragma unroll
            for (int qq = 0; qq < 16; qq++) {
                float4 w = wc[qq];
                outacc[qq*4+0] = fmaf(w.x, hh, outacc[qq*4+0]);
                outacc[qq*4+1] = fmaf(w.y, hh, outacc[qq*4+1]);
                outacc[qq*4+2] = fmaf(w.z, hh, outacc[qq*4+2]);
                outacc[qq*4+3] = fmaf(w.w, hh, outacc[qq*4+3]);
            }
        }
#pragma unroll
        for (int cch = 0; cch < 64; cch++) {
            float v = xp[(size_t)cch * 262144];  // re-read residual (L1-hot)
            xp[(size_t)cch * 262144] = v + gg2[cch] * (outacc[cch] + b2[cch]);
        }
    }
}

// ---------------------------------------------------------------------------
extern "C" void kernel_launch(void* const* d_in, const int* in_sizes, int n_in,
                              void* d_out, int out_size) {
    const float* x         = (const float*)d_in[0];
    const float* c         = (const float*)d_in[1];
    const float* sup_w     = (const float*)d_in[2];
    const float* sup_b     = (const float*)d_in[3];
    const float* qkv_w     = (const float*)d_in[4];
    const float* qkv_b     = (const float*)d_in[5];
    const float* out_w     = (const float*)d_in[6];
    const float* out_b     = (const float*)d_in[7];
    const float* recov_w   = (const float*)d_in[8];
    const float* recov_b   = (const float*)d_in[9];
    const float* ada_att_w = (const float*)d_in[10];
    const float* ada_att_b = (const float*)d_in[11];
    const float* ada_mlp_w = (const float*)d_in[12];
    const float* ada_mlp_b = (const float*)d_in[13];
    const float* fc1_w     = (const float*)d_in[14];
    const float* fc1_b     = (const float*)d_in[15];
    const float* fc2_w     = (const float*)d_in[16];
    const float* fc2_b     = (const float*)d_in[17];
    float* outp = (float*)d_out;

    cudaFuncSetAttribute(k_recov, cudaFuncAttributeMaxDynamicSharedMemorySize, 51200);
    cudaFuncSetAttribute(k_mlp,   cudaFuncAttributeMaxDynamicSharedMemorySize, 100352);

    float *p_xt, *p_qkv, *p_attn, *p_o, *p_attm;
    cudaGetSymbolAddress((void**)&p_xt,   g_xt);
    cudaGetSymbolAddress((void**)&p_qkv,  g_qkv);
    cudaGetSymbolAddress((void**)&p_attn, g_attn);
    cudaGetSymbolAddress((void**)&p_o,    g_o);
    cudaGetSymbolAddress((void**)&p_attm, g_attm);

    k_ada<<<1, 256>>>(c, ada_att_w, ada_att_b, ada_mlp_w, ada_mlp_b);
    k_ropetab<<<64, 256>>>();
    k_sup<<<dim3(8, 32, 2), 128>>>(x, sup_w, sup_b);
    k_ln_mod<<<dim3(8, 2), 128>>>();
    k_gemm64<<<dim3(12, 32), 256>>>(p_xt, qkv_w, qkv_b, p_qkv, 768, 256, nullptr);
    k_rope<<<1024, 256>>>();
    k_attn<<<dim3(8, 8, 2), 128>>>();
    k_gemm64<<<dim3(4, 32), 256>>>(p_attn, out_w, out_b, p_o, 256, 256, p_attm + 512);
    k_upnorm<<<dim3(8, 2), 128>>>();
    k_recov<<<dim3(8, 32, 2), 128, 51200>>>(x, recov_w, recov_b, outp);
    k_mlp<<<dim3(8, 32, 2), 128, 100352>>>(outp, fc1_w, fc1_b, fc2_w, fc2_b);
}

// round 4
// speedup vs baseline: 1.5415x; 1.5415x over previous
#include <cuda_runtime.h>
#include <math.h>

// ---------------------------------------------------------------------------
// FullTimeAtt: B=2, C=64, F=256, T=1024, R=8, SUP=8, Fatt=32, D=256, H=8, hd=32
// fp32 with packed f32x2 FFMA (full precision, 2x FMA-pipe throughput).
// ---------------------------------------------------------------------------

typedef unsigned long long u64t;

__device__ __forceinline__ u64t ffma2(u64t a, u64t b, u64t c) {
    u64t d;
    asm("fma.rn.f32x2 %0, %1, %2, %3;" : "=l"(d) : "l"(a), "l"(b), "l"(c));
    return d;
}
__device__ __forceinline__ u64t fmul2(u64t a, u64t b) {
    u64t d;
    asm("mul.rn.f32x2 %0, %1, %2;" : "=l"(d) : "l"(a), "l"(b));
    return d;
}
__device__ __forceinline__ u64t fpk(float lo, float hi) {
    u64t r;
    asm("mov.b64 %0, {%1, %2};" : "=l"(r) : "f"(lo), "f"(hi));
    return r;
}
__device__ __forceinline__ void fupk(u64t v, float& a, float& b) {
    asm("mov.b64 {%0, %1}, %2;" : "=f"(a), "=f"(b) : "l"(v));
}
__device__ __forceinline__ float fsum2(u64t v) {
    float a, b;
    fupk(v, a, b);
    return a + b;
}

__device__ float g_attm[2 * 768];          // shift|scale|gate (attention adaLN)
__device__ float g_mlpm[2 * 192];          // sh2|sc2|g2 (mlp adaLN)
__device__ float g_cos[1024 * 16];
__device__ float g_sin[1024 * 16];
__device__ float g_xf  [2 * 256 * 1024];   // [b][d][t] after sup-GLU
__device__ float g_xt  [2 * 1024 * 256];   // [b][t][d] after LN+modulate
__device__ float g_qkv [2 * 1024 * 768];   // [b][t][3*256] (rope applied in gemm)
__device__ float g_attn[2 * 1024 * 256];   // [b][t][d] attention output
__device__ float g_o   [2 * 1024 * 256];   // [b][t][d] gated projected
__device__ float g_ln2 [2 * 256 * 1024];   // [b][d][t] after up_norm
__device__ float g_pacc[2 * 2 * 8 * 1024 * 32]; // split-kv partial acc
__device__ float g_pml [2 * 2 * 8 * 1024 * 2];  // split-kv partial (m,l)

// ---------------------------------------------------------------------------
// K0: adaLN matvecs, one warp per output (1920 warps)
// ---------------------------------------------------------------------------
__global__ void k_ada(const float* __restrict__ c,
                      const float* __restrict__ aw, const float* __restrict__ ab,
                      const float* __restrict__ mw, const float* __restrict__ mb) {
    int wid = (blockIdx.x * blockDim.x + threadIdx.x) >> 5;
    int lane = threadIdx.x & 31;
    if (wid >= 1920) return;
    const float* w;
    const float* bia;
    float* dst;
    int b, o;
    if (wid < 1536) {
        b = wid / 768; o = wid % 768;
        w = aw + (size_t)o * 512; bia = ab; dst = g_attm + wid;
    } else {
        int i = wid - 1536;
        b = i / 192; o = i % 192;
        w = mw + (size_t)o * 512; bia = mb; dst = g_mlpm + i;
    }
    const float* cb = c + b * 512;
    float acc = 0.f;
    for (int k = lane; k < 512; k += 32) {
        float v = cb[k];
        float s = v / (1.f + __expf(-v));
        acc = fmaf(s, w[k], acc);
    }
#pragma unroll
    for (int off = 16; off; off >>= 1) acc += __shfl_xor_sync(0xffffffffu, acc, off);
    if (lane == 0) dst[0] = acc + bia[o];
}

// ---------------------------------------------------------------------------
// K0b: RoPE tables
// ---------------------------------------------------------------------------
__global__ void k_ropetab() {
    int idx = blockIdx.x * 256 + threadIdx.x;  // 16384
    int t = idx >> 4, j = idx & 15;
    float inv = (float)(1.0 / pow(10000.0, (double)(2 * j) / 32.0));
    float ang = (float)t * inv;
    float s, cc;
    sincosf(ang, &s, &cc);
    g_cos[idx] = cc;
    g_sin[idx] = s;
}

// ---------------------------------------------------------------------------
// K1: LN over C + pixel-unshuffle + sup 16x512 matvec + GLU (f32x2)
// ---------------------------------------------------------------------------
__global__ void k_sup(const float* __restrict__ x,
                      const float* __restrict__ sup_w,
                      const float* __restrict__ sup_b) {
    __shared__ __align__(16) float wt[512 * 16];  // wt[cr*16+o] = sup_w[o][cr]
    __shared__ float bs[16];
    int tid = threadIdx.x;
    int b = blockIdx.z, fa = blockIdx.y;
    int t = blockIdx.x * 128 + tid;
    for (int i = tid; i < 512 * 16; i += 128) {
        int o = i >> 9, cr = i & 511;
        wt[cr * 16 + o] = sup_w[i];
    }
    if (tid < 16) bs[tid] = sup_b[tid];
    __syncthreads();

    const float* xb = x + ((size_t)(b * 64) * 256 + fa * 8) * 1024 + t;

    float s1[8], s2[8];
#pragma unroll
    for (int r = 0; r < 8; r++) { s1[r] = 0.f; s2[r] = 0.f; }
    for (int cch = 0; cch < 64; cch++) {
#pragma unroll
        for (int r = 0; r < 8; r++) {
            float v = xb[(size_t)(cch * 256 + r) * 1024];
            s1[r] += v;
            s2[r] = fmaf(v, v, s2[r]);
        }
    }
    float mu[8], rs[8];
#pragma unroll
    for (int r = 0; r < 8; r++) {
        mu[r] = s1[r] * (1.f / 64.f);
        float var = s2[r] * (1.f / 64.f) - mu[r] * mu[r];
        rs[r] = rsqrtf(var + 1e-6f);
    }

    u64t acc2[8];
#pragma unroll
    for (int q = 0; q < 8; q++) acc2[q] = 0ull;
    for (int cch = 0; cch < 64; cch++) {
#pragma unroll
        for (int r = 0; r < 8; r++) {
            float xn = (xb[(size_t)(cch * 256 + r) * 1024] - mu[r]) * rs[r];
            u64t x2 = fpk(xn, xn);
            const u64t* wp = (const u64t*)(wt + (cch * 8 + r) * 16);
#pragma unroll
            for (int q = 0; q < 8; q++) acc2[q] = ffma2(x2, wp[q], acc2[q]);
        }
    }
    float accv[16];
#pragma unroll
    for (int q = 0; q < 8; q++) fupk(acc2[q], accv[2 * q], accv[2 * q + 1]);
#pragma unroll
    for (int s = 0; s < 8; s++) {
        float ya = accv[s] + bs[s];
        float yb = accv[s + 8] + bs[s + 8];
        float outv = ya * (yb / (1.f + __expf(-yb)));
        g_xf[((size_t)(b * 256) + (s * 32 + fa)) * 1024 + t] = outv;
    }
}

// ---------------------------------------------------------------------------
// K2: LN over D=256 + modulate; [b][d][t] -> [b][t][d]. Tiled transpose,
// 32 t per block, coalesced both sides.
// ---------------------------------------------------------------------------
__global__ void k_ln_mod() {
    __shared__ __align__(16) float sm[256][33];
    __shared__ float shs[256], scs[256];
    __shared__ float red1[8][32], red2[8][32];
    __shared__ float smu[32], srs[32];
    int tid = threadIdx.x;  // 256
    int b = blockIdx.y;
    int t0 = blockIdx.x * 32;
    for (int i = tid; i < 256; i += 256) {
        shs[i] = g_attm[b * 768 + i];
        scs[i] = 1.f + g_attm[b * 768 + 256 + i];
    }
    for (int i = tid; i < 8192; i += 256) {
        int d = i >> 5, tt = i & 31;
        sm[d][tt] = g_xf[(size_t)(b * 256 + d) * 1024 + t0 + tt];
    }
    __syncthreads();
    int col = tid & 31, part = tid >> 5;
    float s1 = 0.f, s2 = 0.f;
    for (int j = 0; j < 32; j++) {
        float v = sm[part * 32 + j][col];
        s1 += v;
        s2 = fmaf(v, v, s2);
    }
    red1[part][col] = s1;
    red2[part][col] = s2;
    __syncthreads();
    if (tid < 32) {
        float a = 0.f, c2 = 0.f;
        for (int p = 0; p < 8; p++) { a += red1[p][tid]; c2 += red2[p][tid]; }
        float mu = a * (1.f / 256.f);
        smu[tid] = mu;
        srs[tid] = rsqrtf(c2 * (1.f / 256.f) - mu * mu + 1e-6f);
    }
    __syncthreads();
    for (int i = tid; i < 8192; i += 256) {
        int tt = i >> 8, d = i & 255;
        float v = (sm[d][tt] - smu[tt]) * srs[tt] * scs[d] + shs[d];
        g_xt[((size_t)(b * 1024) + t0 + tt) * 256 + d] = v;
    }
}

// ---------------------------------------------------------------------------
// K3/K5: NT GEMM C[M][N] = A[M][K] @ W[N][K]^T + bias, f32x2 inner.
// 64x64 tile, BK=16, 256 threads, 4x2pair micro. rope: rotate cols<512.
// gate: C *= gate[(row>>10)*768 + col]
// ---------------------------------------------------------------------------
__global__ void k_gemm64(const float* __restrict__ A, const float* __restrict__ W,
                         const float* __restrict__ bias, float* __restrict__ C,
                         int N, int K, const float* __restrict__ gate, int rope) {
    __shared__ __align__(16) float As[64][17];
    __shared__ __align__(16) float Wst[16][66];
    int tid = threadIdx.x;
    int row0 = blockIdx.y * 64, col0 = blockIdx.x * 64;
    int ty = tid >> 4, tx = tid & 15;
    int lr = tid >> 2, lk = (tid & 3) * 4;
    u64t acc2[4][2];
#pragma unroll
    for (int i = 0; i < 4; i++) { acc2[i][0] = 0ull; acc2[i][1] = 0ull; }

    for (int k0 = 0; k0 < K; k0 += 16) {
        float4 av = *(const float4*)(A + (size_t)(row0 + lr) * K + k0 + lk);
        float4 wv = *(const float4*)(W + (size_t)(col0 + lr) * K + k0 + lk);
        __syncthreads();
        As[lr][lk + 0] = av.x; As[lr][lk + 1] = av.y; As[lr][lk + 2] = av.z; As[lr][lk + 3] = av.w;
        Wst[lk + 0][lr] = wv.x; Wst[lk + 1][lr] = wv.y; Wst[lk + 2][lr] = wv.z; Wst[lk + 3][lr] = wv.w;
        __syncthreads();
#pragma unroll
        for (int kk = 0; kk < 16; kk++) {
            const u64t* wr = (const u64t*)(&Wst[kk][0]);
            u64t b0 = wr[tx * 2], b1 = wr[tx * 2 + 1];
#pragma unroll
            for (int i = 0; i < 4; i++) {
                float a = As[ty * 4 + i][kk];
                u64t a2 = fpk(a, a);
                acc2[i][0] = ffma2(a2, b0, acc2[i][0]);
                acc2[i][1] = ffma2(a2, b1, acc2[i][1]);
            }
        }
    }
#pragma unroll
    for (int i = 0; i < 4; i++) {
        int r = row0 + ty * 4 + i;
        int t = r & 1023;
#pragma unroll
        for (int p = 0; p < 2; p++) {
            float v0, v1;
            fupk(acc2[i][p], v0, v1);
            int cc = col0 + tx * 4 + p * 2;
            v0 += bias[cc];
            v1 += bias[cc + 1];
            if (rope && cc < 512) {
                int j = (cc & 31) >> 1;
                float co = g_cos[t * 16 + j], si = g_sin[t * 16 + j];
                float r0 = v0 * co - v1 * si;
                float r1 = v0 * si + v1 * co;
                v0 = r0; v1 = r1;
            }
            if (gate) {
                v0 *= gate[(r >> 10) * 768 + cc];
                v1 *= gate[(r >> 10) * 768 + cc + 1];
            }
            float2 st; st.x = v0; st.y = v1;
            *(float2*)(C + (size_t)r * N + cc) = st;
        }
    }
}

// ---------------------------------------------------------------------------
// K4: split-KV attention partials. block (qtile8, h8, b*2+sp), 128 thr.
// ---------------------------------------------------------------------------
__global__ void k_attn2() {
    __shared__ __align__(16) float ks[32][32];
    __shared__ __align__(16) float vs[32][32];
    int tid = threadIdx.x;
    int z = blockIdx.z;
    int b = z >> 1, sp = z & 1;
    int h = blockIdx.y;
    int t = blockIdx.x * 128 + tid;
    const float* qp = g_qkv + ((size_t)(b * 1024) + t) * 768 + h * 32;
    u64t q2[16];
    const u64t* qq = (const u64t*)qp;
#pragma unroll
    for (int i = 0; i < 16; i++) q2[i] = qq[i];
    float m = -1e30f, l = 0.f;
    u64t acc2[16];
#pragma unroll
    for (int i = 0; i < 16; i++) acc2[i] = 0ull;
    const float scale = 0.17677669529663689f;  // 32^-0.5

    int s_begin = sp * 512;
    for (int st0 = s_begin; st0 < s_begin + 512; st0 += 32) {
        __syncthreads();
        for (int i = tid; i < 256; i += 128) {
            int rr = i >> 3, c4 = (i & 7) * 4;
            const float* kb = g_qkv + ((size_t)(b * 1024) + st0 + rr) * 768 + 256 + h * 32 + c4;
            *(float4*)(&ks[rr][c4]) = *(const float4*)kb;
            *(float4*)(&vs[rr][c4]) = *(const float4*)(kb + 256);
        }
        __syncthreads();
        float scl[32];
        float tmax = -1e30f;
#pragma unroll
        for (int s = 0; s < 32; s++) {
            const u64t* kr = (const u64t*)(&ks[s][0]);
            u64t da = 0ull, db = 0ull;
#pragma unroll
            for (int q = 0; q < 16; q += 2) {
                da = ffma2(q2[q], kr[q], da);
                db = ffma2(q2[q + 1], kr[q + 1], db);
            }
            float dot = (fsum2(da) + fsum2(db)) * scale;
            scl[s] = dot;
            tmax = fmaxf(tmax, dot);
        }
        float mn = fmaxf(m, tmax);
        float corr = __expf(m - mn);
        l *= corr;
        u64t c2 = fpk(corr, corr);
#pragma unroll
        for (int i = 0; i < 16; i++) acc2[i] = fmul2(acc2[i], c2);
#pragma unroll
        for (int s = 0; s < 32; s++) {
            float p = __expf(scl[s] - mn);
            l += p;
            u64t p2 = fpk(p, p);
            const u64t* vr = (const u64t*)(&vs[s][0]);
#pragma unroll
            for (int i = 0; i < 16; i++) acc2[i] = ffma2(p2, vr[i], acc2[i]);
        }
        m = mn;
    }
    int r0 = sp * 16384 + (b * 8 + h) * 1024 + t;
    g_pml[r0 * 2] = m;
    g_pml[r0 * 2 + 1] = l;
    float* op = g_pacc + (size_t)r0 * 32;
#pragma unroll
    for (int i = 0; i < 16; i += 2) {
        float4 o;
        fupk(acc2[i], o.x, o.y);
        fupk(acc2[i + 1], o.z, o.w);
        *(float4*)(op + 2 * i) = o;
    }
}

// ---------------------------------------------------------------------------
// K4b: combine split-KV partials -> g_attn[b][t][h*32+d]
// ---------------------------------------------------------------------------
__global__ void k_attn_comb() {
    int idx = blockIdx.x * 256 + threadIdx.x;  // 131072
    int row = idx >> 3, q4 = idx & 7;
    int b = row >> 13, rem = row & 8191;
    int h = rem >> 10, t = rem & 1023;
    int r0 = (b * 8 + h) * 1024 + t;
    float m1 = g_pml[r0 * 2], l1 = g_pml[r0 * 2 + 1];
    float m2 = g_pml[(16384 + r0) * 2], l2 = g_pml[(16384 + r0) * 2 + 1];
    float mM = fmaxf(m1, m2);
    float e1 = __expf(m1 - mM), e2 = __expf(m2 - mM);
    float inv = 1.f / (l1 * e1 + l2 * e2);
    float4 a1 = ((const float4*)g_pacc)[(size_t)r0 * 8 + q4];
    float4 a2 = ((const float4*)g_pacc)[(size_t)(16384 + r0) * 8 + q4];
    float4 o;
    o.x = (a1.x * e1 + a2.x * e2) * inv;
    o.y = (a1.y * e1 + a2.y * e2) * inv;
    o.z = (a1.z * e1 + a2.z * e2) * inv;
    o.w = (a1.w * e1 + a2.w * e2) * inv;
    ((float4*)g_attn)[(((size_t)(b * 1024) + t) * 256 + h * 32) / 4 + q4] = o;
}

// ---------------------------------------------------------------------------
// K5b: up_norm — LN over D; [b][t][d] -> [b][d][t]. Tiled transpose.
// ---------------------------------------------------------------------------
__global__ void k_upnorm() {
    __shared__ __align__(16) float sm[256][33];
    __shared__ float red1[8][32], red2[8][32];
    __shared__ float smu[32], srs[32];
    int tid = threadIdx.x;  // 256
    int b = blockIdx.y;
    int t0 = blockIdx.x * 32;
    for (int i = tid; i < 8192; i += 256) {
        int tt = i >> 8, d = i & 255;
        sm[d][tt] = g_o[((size_t)(b * 1024) + t0 + tt) * 256 + d];
    }
    __syncthreads();
    int col = tid & 31, part = tid >> 5;
    float s1 = 0.f, s2 = 0.f;
    for (int j = 0; j < 32; j++) {
        float v = sm[part * 32 + j][col];
        s1 += v;
        s2 = fmaf(v, v, s2);
    }
    red1[part][col] = s1;
    red2[part][col] = s2;
    __syncthreads();
    if (tid < 32) {
        float a = 0.f, c2 = 0.f;
        for (int p = 0; p < 8; p++) { a += red1[p][tid]; c2 += red2[p][tid]; }
        float mu = a * (1.f / 256.f);
        smu[tid] = mu;
        srs[tid] = rsqrtf(c2 * (1.f / 256.f) - mu * mu + 1e-6f);
    }
    __syncthreads();
    for (int i = tid; i < 8192; i += 256) {
        int d = i >> 5, tt = i & 31;
        g_ln2[(size_t)(b * 256 + d) * 1024 + t0 + tt] = (sm[d][tt] - smu[tt]) * srs[tt];
    }
}

// ---------------------------------------------------------------------------
// K6: recov conv(3,1) + pixel-shuffle + residual -> out (f32x2)
// ---------------------------------------------------------------------------
__global__ void k_recov(const float* __restrict__ x,
                        const float* __restrict__ rw,
                        const float* __restrict__ rb,
                        float* __restrict__ outp) {
    extern __shared__ float sm6[];
    float* ws = sm6;             // [512][24]
    float* bbs = sm6 + 512 * 24;
    int tid = threadIdx.x;
    int b = blockIdx.z, fa = blockIdx.y;
    int t = blockIdx.x * 128 + tid;
    for (int i = tid; i < 3072; i += 128) ((float4*)ws)[i] = ((const float4*)rw)[i];
    for (int i = tid; i < 512; i += 128) bbs[i] = rb[i];
    __syncthreads();

    float xv[24];
#pragma unroll
    for (int i = 0; i < 8; i++) {
#pragma unroll
        for (int kh = 0; kh < 3; kh++) {
            int fs = fa + kh - 1;
            xv[i * 3 + kh] = (fs >= 0 && fs < 32)
                ? g_ln2[((size_t)(b * 256) + i * 32 + fs) * 1024 + t] : 0.f;
        }
    }
    u64t xv2[12];
#pragma unroll
    for (int q = 0; q < 12; q++) xv2[q] = fpk(xv[2 * q], xv[2 * q + 1]);

    for (int o = 0; o < 512; o++) {
        const u64t* wp = (const u64t*)(ws + o * 24);
        u64t aa = 0ull, bb2 = 0ull;
#pragma unroll
        for (int q = 0; q < 12; q += 2) {
            aa = ffma2(xv2[q], wp[q], aa);
            bb2 = ffma2(xv2[q + 1], wp[q + 1], bb2);
        }
        float accv = fsum2(aa) + fsum2(bb2) + bbs[o];
        int cch = o >> 3, r = o & 7;
        size_t idx = ((size_t)(b * 64 + cch) * 256 + fa * 8 + r) * 1024 + t;
        outp[idx] = x[idx] + accv;
    }
}

// ---------------------------------------------------------------------------
// K7: gated MLP in place on out (x_mid), f32x2 inner loops.
// ---------------------------------------------------------------------------
__global__ void __launch_bounds__(128)
k_mlp(float* __restrict__ xio,
      const float* __restrict__ fc1w, const float* __restrict__ fc1b,
      const float* __restrict__ fc2w, const float* __restrict__ fc2b) {
    extern __shared__ float sm7[];
    float* w1  = sm7;                   // [256][64]
    float* w2t = sm7 + 16384;           // [128][64] transposed fc2
    float* b1  = sm7 + 16384 + 8192;    // 256
    float* b2  = b1 + 256;              // 64
    float* sh2 = b2 + 64;               // 64
    float* sc2 = sh2 + 64;              // 64
    float* gg2 = sc2 + 64;              // 64
    int tid = threadIdx.x;
    int b = blockIdx.z, fg = blockIdx.y;
    int t = blockIdx.x * 128 + tid;
    for (int i = tid; i < 4096; i += 128) ((float4*)w1)[i] = ((const float4*)fc1w)[i];
    for (int i = tid; i < 8192; i += 128) {
        int c2 = i >> 7, o = i & 127;
        w2t[o * 64 + c2] = fc2w[i];
    }
    for (int i = tid; i < 256; i += 128) b1[i] = fc1b[i];
    if (tid < 64) {
        b2[tid]  = fc2b[tid];
        sh2[tid] = g_mlpm[b * 192 + tid];
        sc2[tid] = g_mlpm[b * 192 + 64 + tid];
        gg2[tid] = g_mlpm[b * 192 + 128 + tid];
    }
    __syncthreads();

    for (int fi = 0; fi < 8; fi++) {
        int f = fg * 8 + fi;
        float* xp = xio + ((size_t)(b * 64) * 256 + f) * 1024 + t;

        float mm[64];
        float s1 = 0.f, s2v = 0.f;
#pragma unroll
        for (int cch = 0; cch < 64; cch++) {
            float v = xp[(size_t)cch * 262144];
            mm[cch] = v;
            s1 += v;
            s2v = fmaf(v, v, s2v);
        }
        float mu = s1 * (1.f / 64.f);
        float rs = rsqrtf(s2v * (1.f / 64.f) - mu * mu + 1e-6f);
        u64t mm2[32];
#pragma unroll
        for (int q = 0; q < 32; q++) {
            float a = (mm[2 * q] - mu) * rs * (1.f + sc2[2 * q]) + sh2[2 * q];
            float bb = (mm[2 * q + 1] - mu) * rs * (1.f + sc2[2 * q + 1]) + sh2[2 * q + 1];
            mm2[q] = fpk(a, bb);
        }

        u64t outacc2[32];
#pragma unroll
        for (int q = 0; q < 32; q++) outacc2[q] = 0ull;

        for (int o = 0; o < 128; o++) {
            const u64t* wa = (const u64t*)(w1 + o * 64);
            const u64t* wb = (const u64t*)(w1 + (o + 128) * 64);
            u64t ua = 0ull, ub = 0ull, ga = 0ull, gb = 0ull;
#pragma unroll
            for (int q = 0; q < 32; q += 2) {
                ua = ffma2(wa[q], mm2[q], ua);
                ub = ffma2(wa[q + 1], mm2[q + 1], ub);
                ga = ffma2(wb[q], mm2[q], ga);
                gb = ffma2(wb[q + 1], mm2[q + 1], gb);
            }
            float u = fsum2(ua) + fsum2(ub) + b1[o];
            float g = fsum2(ga) + fsum2(gb) + b1[o + 128];
            float hh = u * (g / (1.f + __expf(-g)));
            u64t h2 = fpk(hh, hh);
            const u64t* wc = (const u64t*)(w2t + o * 64);
#pragma unroll
            for (int q = 0; q < 32; q++) outacc2[q] = ffma2(wc[q], h2, outacc2[q]);
        }
#pragma unroll
        for (int q = 0; q < 32; q++) {
            float o0, o1;
            fupk(outacc2[q], o0, o1);
            float v0 = xp[(size_t)(2 * q) * 262144];
            float v1 = xp[(size_t)(2 * q + 1) * 262144];
            xp[(size_t)(2 * q) * 262144]     = v0 + gg2[2 * q]     * (o0 + b2[2 * q]);
            xp[(size_t)(2 * q + 1) * 262144] = v1 + gg2[2 * q + 1] * (o1 + b2[2 * q + 1]);
        }
    }
}

// ---------------------------------------------------------------------------
extern "C" void kernel_launch(void* const* d_in, const int* in_sizes, int n_in,
                              void* d_out, int out_size) {
    const float* x         = (const float*)d_in[0];
    const float* c         = (const float*)d_in[1];
    const float* sup_w     = (const float*)d_in[2];
    const float* sup_b     = (const float*)d_in[3];
    const float* qkv_w     = (const float*)d_in[4];
    const float* qkv_b     = (const float*)d_in[5];
    const float* out_w     = (const float*)d_in[6];
    const float* out_b     = (const float*)d_in[7];
    const float* recov_w   = (const float*)d_in[8];
    const float* recov_b   = (const float*)d_in[9];
    const float* ada_att_w = (const float*)d_in[10];
    const float* ada_att_b = (const float*)d_in[11];
    const float* ada_mlp_w = (const float*)d_in[12];
    const float* ada_mlp_b = (const float*)d_in[13];
    const float* fc1_w     = (const float*)d_in[14];
    const float* fc1_b     = (const float*)d_in[15];
    const float* fc2_w     = (const float*)d_in[16];
    const float* fc2_b     = (const float*)d_in[17];
    float* outp = (float*)d_out;

    cudaFuncSetAttribute(k_recov, cudaFuncAttributeMaxDynamicSharedMemorySize, 51200);
    cudaFuncSetAttribute(k_mlp,   cudaFuncAttributeMaxDynamicSharedMemorySize, 100352);

    float *p_xt, *p_qkv, *p_attn, *p_o, *p_attm;
    cudaGetSymbolAddress((void**)&p_xt,   g_xt);
    cudaGetSymbolAddress((void**)&p_qkv,  g_qkv);
    cudaGetSymbolAddress((void**)&p_attn, g_attn);
    cudaGetSymbolAddress((void**)&p_o,    g_o);
    cudaGetSymbolAddress((void**)&p_attm, g_attm);

    k_ada<<<240, 256>>>(c, ada_att_w, ada_att_b, ada_mlp_w, ada_mlp_b);
    k_ropetab<<<64, 256>>>();
    k_sup<<<dim3(8, 32, 2), 128>>>(x, sup_w, sup_b);
    k_ln_mod<<<dim3(32, 2), 256>>>();
    k_gemm64<<<dim3(12, 32), 256>>>(p_xt, qkv_w, qkv_b, p_qkv, 768, 256, nullptr, 1);
    k_attn2<<<dim3(8, 8, 4), 128>>>();
    k_attn_comb<<<512, 256>>>();
    k_gemm64<<<dim3(4, 32), 256>>>(p_attn, out_w, out_b, p_o, 256, 256, p_attm + 512, 0);
    k_upnorm<<<dim3(32, 2), 256>>>();
    k_recov<<<dim3(8, 32, 2), 128, 51200>>>(x, recov_w, recov_b, outp);
    k_mlp<<<dim3(8, 32, 2), 128, 100352>>>(outp, fc1_w, fc1_b, fc2_w, fc2_b);
}

// round 5
// speedup vs baseline: 2.6597x; 1.7254x over previous
#include <cuda_runtime.h>
#include <math.h>

// ---------------------------------------------------------------------------
// FullTimeAtt: B=2, C=64, F=256, T=1024, R=8, SUP=8, Fatt=32, D=256, H=8, hd=32
// fp32 with packed f32x2 FFMA. MLP restructured as register-tiled fused GEMMs.
// ---------------------------------------------------------------------------

typedef unsigned long long u64t;

__device__ __forceinline__ u64t ffma2(u64t a, u64t b, u64t c) {
    u64t d;
    asm("fma.rn.f32x2 %0, %1, %2, %3;" : "=l"(d) : "l"(a), "l"(b), "l"(c));
    return d;
}
__device__ __forceinline__ u64t fmul2(u64t a, u64t b) {
    u64t d;
    asm("mul.rn.f32x2 %0, %1, %2;" : "=l"(d) : "l"(a), "l"(b));
    return d;
}
__device__ __forceinline__ u64t fpk(float lo, float hi) {
    u64t r;
    asm("mov.b64 %0, {%1, %2};" : "=l"(r) : "f"(lo), "f"(hi));
    return r;
}
__device__ __forceinline__ void fupk(u64t v, float& a, float& b) {
    asm("mov.b64 {%0, %1}, %2;" : "=f"(a), "=f"(b) : "l"(v));
}
__device__ __forceinline__ float fsum2(u64t v) {
    float a, b;
    fupk(v, a, b);
    return a + b;
}

__device__ float g_attm[2 * 768];          // shift|scale|gate (attention adaLN)
__device__ float g_mlpm[2 * 192];          // sh2|sc2|g2 (mlp adaLN)
__device__ float g_cos[1024 * 16];
__device__ float g_sin[1024 * 16];
__device__ float g_xf  [2 * 256 * 1024];   // [b][d][t] after sup-GLU
__device__ float g_xt  [2 * 1024 * 256];   // [b][t][d] after LN+modulate
__device__ float g_qkv [2 * 1024 * 768];   // [b][t][3*256] (rope applied in gemm)
__device__ float g_attn[2 * 1024 * 256];   // [b][t][d] attention output
__device__ float g_o   [2 * 1024 * 256];   // [b][t][d] gated projected
__device__ float g_ln2 [2 * 256 * 1024];   // [b][d][t] after up_norm
__device__ float g_pacc[2 * 2 * 8 * 1024 * 32]; // split-kv partial acc
__device__ float g_pml [2 * 2 * 8 * 1024 * 2];  // split-kv partial (m,l)

// ---------------------------------------------------------------------------
// K0: adaLN matvecs, one warp per output (1920 warps)
// ---------------------------------------------------------------------------
__global__ void k_ada(const float* __restrict__ c,
                      const float* __restrict__ aw, const float* __restrict__ ab,
                      const float* __restrict__ mw, const float* __restrict__ mb) {
    int wid = (blockIdx.x * blockDim.x + threadIdx.x) >> 5;
    int lane = threadIdx.x & 31;
    if (wid >= 1920) return;
    const float* w;
    const float* bia;
    float* dst;
    int b, o;
    if (wid < 1536) {
        b = wid / 768; o = wid % 768;
        w = aw + (size_t)o * 512; bia = ab; dst = g_attm + wid;
    } else {
        int i = wid - 1536;
        b = i / 192; o = i % 192;
        w = mw + (size_t)o * 512; bia = mb; dst = g_mlpm + i;
    }
    const float* cb = c + b * 512;
    float acc = 0.f;
    for (int k = lane; k < 512; k += 32) {
        float v = cb[k];
        float s = v / (1.f + __expf(-v));
        acc = fmaf(s, w[k], acc);
    }
#pragma unroll
    for (int off = 16; off; off >>= 1) acc += __shfl_xor_sync(0xffffffffu, acc, off);
    if (lane == 0) dst[0] = acc + bia[o];
}

// ---------------------------------------------------------------------------
// K0b: RoPE tables
// ---------------------------------------------------------------------------
__global__ void k_ropetab() {
    int idx = blockIdx.x * 256 + threadIdx.x;  // 16384
    int t = idx >> 4, j = idx & 15;
    float inv = (float)(1.0 / pow(10000.0, (double)(2 * j) / 32.0));
    float ang = (float)t * inv;
    float s, cc;
    sincosf(ang, &s, &cc);
    g_cos[idx] = cc;
    g_sin[idx] = s;
}

// ---------------------------------------------------------------------------
// K1: LN over C + pixel-unshuffle + sup 16x512 matvec + GLU (f32x2)
// ---------------------------------------------------------------------------
__global__ void k_sup(const float* __restrict__ x,
                      const float* __restrict__ sup_w,
                      const float* __restrict__ sup_b) {
    __shared__ __align__(16) float wt[512 * 16];  // wt[cr*16+o] = sup_w[o][cr]
    __shared__ float bs[16];
    int tid = threadIdx.x;
    int b = blockIdx.z, fa = blockIdx.y;
    int t = blockIdx.x * 128 + tid;
    for (int i = tid; i < 512 * 16; i += 128) {
        int o = i >> 9, cr = i & 511;
        wt[cr * 16 + o] = sup_w[i];
    }
    if (tid < 16) bs[tid] = sup_b[tid];
    __syncthreads();

    const float* xb = x + ((size_t)(b * 64) * 256 + fa * 8) * 1024 + t;

    float s1[8], s2[8];
#pragma unroll
    for (int r = 0; r < 8; r++) { s1[r] = 0.f; s2[r] = 0.f; }
    for (int cch = 0; cch < 64; cch++) {
#pragma unroll
        for (int r = 0; r < 8; r++) {
            float v = xb[(size_t)(cch * 256 + r) * 1024];
            s1[r] += v;
            s2[r] = fmaf(v, v, s2[r]);
        }
    }
    float mu[8], rs[8];
#pragma unroll
    for (int r = 0; r < 8; r++) {
        mu[r] = s1[r] * (1.f / 64.f);
        float var = s2[r] * (1.f / 64.f) - mu[r] * mu[r];
        rs[r] = rsqrtf(var + 1e-6f);
    }

    u64t acc2[8];
#pragma unroll
    for (int q = 0; q < 8; q++) acc2[q] = 0ull;
    for (int cch = 0; cch < 64; cch++) {
#pragma unroll
        for (int r = 0; r < 8; r++) {
            float xn = (xb[(size_t)(cch * 256 + r) * 1024] - mu[r]) * rs[r];
            u64t x2 = fpk(xn, xn);
            const u64t* wp = (const u64t*)(wt + (cch * 8 + r) * 16);
#pragma unroll
            for (int q = 0; q < 8; q++) acc2[q] = ffma2(x2, wp[q], acc2[q]);
        }
    }
    float accv[16];
#pragma unroll
    for (int q = 0; q < 8; q++) fupk(acc2[q], accv[2 * q], accv[2 * q + 1]);
#pragma unroll
    for (int s = 0; s < 8; s++) {
        float ya = accv[s] + bs[s];
        float yb = accv[s + 8] + bs[s + 8];
        float outv = ya * (yb / (1.f + __expf(-yb)));
        g_xf[((size_t)(b * 256) + (s * 32 + fa)) * 1024 + t] = outv;
    }
}

// ---------------------------------------------------------------------------
// K2: LN over D=256 + modulate; [b][d][t] -> [b][t][d]. Tiled transpose.
// ---------------------------------------------------------------------------
__global__ void k_ln_mod() {
    __shared__ __align__(16) float sm[256][33];
    __shared__ float shs[256], scs[256];
    __shared__ float red1[8][32], red2[8][32];
    __shared__ float smu[32], srs[32];
    int tid = threadIdx.x;  // 256
    int b = blockIdx.y;
    int t0 = blockIdx.x * 32;
    for (int i = tid; i < 256; i += 256) {
        shs[i] = g_attm[b * 768 + i];
        scs[i] = 1.f + g_attm[b * 768 + 256 + i];
    }
    for (int i = tid; i < 8192; i += 256) {
        int d = i >> 5, tt = i & 31;
        sm[d][tt] = g_xf[(size_t)(b * 256 + d) * 1024 + t0 + tt];
    }
    __syncthreads();
    int col = tid & 31, part = tid >> 5;
    float s1 = 0.f, s2 = 0.f;
    for (int j = 0; j < 32; j++) {
        float v = sm[part * 32 + j][col];
        s1 += v;
        s2 = fmaf(v, v, s2);
    }
    red1[part][col] = s1;
    red2[part][col] = s2;
    __syncthreads();
    if (tid < 32) {
        float a = 0.f, c2 = 0.f;
        for (int p = 0; p < 8; p++) { a += red1[p][tid]; c2 += red2[p][tid]; }
        float mu = a * (1.f / 256.f);
        smu[tid] = mu;
        srs[tid] = rsqrtf(c2 * (1.f / 256.f) - mu * mu + 1e-6f);
    }
    __syncthreads();
    for (int i = tid; i < 8192; i += 256) {
        int tt = i >> 8, d = i & 255;
        float v = (sm[d][tt] - smu[tt]) * srs[tt] * scs[d] + shs[d];
        g_xt[((size_t)(b * 1024) + t0 + tt) * 256 + d] = v;
    }
}

// ---------------------------------------------------------------------------
// K3/K5: NT GEMM C[M][N] = A[M][K] @ W[N][K]^T + bias, f32x2 inner.
// ---------------------------------------------------------------------------
__global__ void k_gemm64(const float* __restrict__ A, const float* __restrict__ W,
                         const float* __restrict__ bias, float* __restrict__ C,
                         int N, int K, const float* __restrict__ gate, int rope) {
    __shared__ __align__(16) float As[64][17];
    __shared__ __align__(16) float Wst[16][66];
    int tid = threadIdx.x;
    int row0 = blockIdx.y * 64, col0 = blockIdx.x * 64;
    int ty = tid >> 4, tx = tid & 15;
    int lr = tid >> 2, lk = (tid & 3) * 4;
    u64t acc2[4][2];
#pragma unroll
    for (int i = 0; i < 4; i++) { acc2[i][0] = 0ull; acc2[i][1] = 0ull; }

    for (int k0 = 0; k0 < K; k0 += 16) {
        float4 av = *(const float4*)(A + (size_t)(row0 + lr) * K + k0 + lk);
        float4 wv = *(const float4*)(W + (size_t)(col0 + lr) * K + k0 + lk);
        __syncthreads();
        As[lr][lk + 0] = av.x; As[lr][lk + 1] = av.y; As[lr][lk + 2] = av.z; As[lr][lk + 3] = av.w;
        Wst[lk + 0][lr] = wv.x; Wst[lk + 1][lr] = wv.y; Wst[lk + 2][lr] = wv.z; Wst[lk + 3][lr] = wv.w;
        __syncthreads();
#pragma unroll
        for (int kk = 0; kk < 16; kk++) {
            const u64t* wr = (const u64t*)(&Wst[kk][0]);
            u64t b0 = wr[tx * 2], b1 = wr[tx * 2 + 1];
#pragma unroll
            for (int i = 0; i < 4; i++) {
                float a = As[ty * 4 + i][kk];
                u64t a2 = fpk(a, a);
                acc2[i][0] = ffma2(a2, b0, acc2[i][0]);
                acc2[i][1] = ffma2(a2, b1, acc2[i][1]);
            }
        }
    }
#pragma unroll
    for (int i = 0; i < 4; i++) {
        int r = row0 + ty * 4 + i;
        int t = r & 1023;
#pragma unroll
        for (int p = 0; p < 2; p++) {
            float v0, v1;
            fupk(acc2[i][p], v0, v1);
            int cc = col0 + tx * 4 + p * 2;
            v0 += bias[cc];
            v1 += bias[cc + 1];
            if (rope && cc < 512) {
                int j = (cc & 31) >> 1;
                float co = g_cos[t * 16 + j], si = g_sin[t * 16 + j];
                float r0 = v0 * co - v1 * si;
                float r1 = v0 * si + v1 * co;
                v0 = r0; v1 = r1;
            }
            if (gate) {
                v0 *= gate[(r >> 10) * 768 + cc];
                v1 *= gate[(r >> 10) * 768 + cc + 1];
            }
            float2 st; st.x = v0; st.y = v1;
            *(float2*)(C + (size_t)r * N + cc) = st;
        }
    }
}

// ---------------------------------------------------------------------------
// K4: split-KV attention partials. block (qtile8, h8, b*2+sp), 128 thr.
// ---------------------------------------------------------------------------
__global__ void k_attn2() {
    __shared__ __align__(16) float ks[32][32];
    __shared__ __align__(16) float vs[32][32];
    int tid = threadIdx.x;
    int z = blockIdx.z;
    int b = z >> 1, sp = z & 1;
    int h = blockIdx.y;
    int t = blockIdx.x * 128 + tid;
    const float* qp = g_qkv + ((size_t)(b * 1024) + t) * 768 + h * 32;
    u64t q2[16];
    const u64t* qq = (const u64t*)qp;
#pragma unroll
    for (int i = 0; i < 16; i++) q2[i] = qq[i];
    float m = -1e30f, l = 0.f;
    u64t acc2[16];
#pragma unroll
    for (int i = 0; i < 16; i++) acc2[i] = 0ull;
    const float scale = 0.17677669529663689f;  // 32^-0.5

    int s_begin = sp * 512;
    for (int st0 = s_begin; st0 < s_begin + 512; st0 += 32) {
        __syncthreads();
        for (int i = tid; i < 256; i += 128) {
            int rr = i >> 3, c4 = (i & 7) * 4;
            const float* kb = g_qkv + ((size_t)(b * 1024) + st0 + rr) * 768 + 256 + h * 32 + c4;
            *(float4*)(&ks[rr][c4]) = *(const float4*)kb;
            *(float4*)(&vs[rr][c4]) = *(const float4*)(kb + 256);
        }
        __syncthreads();
        float scl[32];
        float tmax = -1e30f;
#pragma unroll
        for (int s = 0; s < 32; s++) {
            const u64t* kr = (const u64t*)(&ks[s][0]);
            u64t da = 0ull, db = 0ull;
#pragma unroll
            for (int q = 0; q < 16; q += 2) {
                da = ffma2(q2[q], kr[q], da);
                db = ffma2(q2[q + 1], kr[q + 1], db);
            }
            float dot = (fsum2(da) + fsum2(db)) * scale;
            scl[s] = dot;
            tmax = fmaxf(tmax, dot);
        }
        float mn = fmaxf(m, tmax);
        float corr = __expf(m - mn);
        l *= corr;
        u64t c2 = fpk(corr, corr);
#pragma unroll
        for (int i = 0; i < 16; i++) acc2[i] = fmul2(acc2[i], c2);
#pragma unroll
        for (int s = 0; s < 32; s++) {
            float p = __expf(scl[s] - mn);
            l += p;
            u64t p2 = fpk(p, p);
            const u64t* vr = (const u64t*)(&vs[s][0]);
#pragma unroll
            for (int i = 0; i < 16; i++) acc2[i] = ffma2(p2, vr[i], acc2[i]);
        }
        m = mn;
    }
    int r0 = sp * 16384 + (b * 8 + h) * 1024 + t;
    g_pml[r0 * 2] = m;
    g_pml[r0 * 2 + 1] = l;
    float* op = g_pacc + (size_t)r0 * 32;
#pragma unroll
    for (int i = 0; i < 16; i += 2) {
        float4 o;
        fupk(acc2[i], o.x, o.y);
        fupk(acc2[i + 1], o.z, o.w);
        *(float4*)(op + 2 * i) = o;
    }
}

// ---------------------------------------------------------------------------
// K4b: combine split-KV partials -> g_attn[b][t][h*32+d]
// ---------------------------------------------------------------------------
__global__ void k_attn_comb() {
    int idx = blockIdx.x * 256 + threadIdx.x;  // 131072
    int row = idx >> 3, q4 = idx & 7;
    int b = row >> 13, rem = row & 8191;
    int h = rem >> 10, t = rem & 1023;
    int r0 = (b * 8 + h) * 1024 + t;
    float m1 = g_pml[r0 * 2], l1 = g_pml[r0 * 2 + 1];
    float m2 = g_pml[(16384 + r0) * 2], l2 = g_pml[(16384 + r0) * 2 + 1];
    float mM = fmaxf(m1, m2);
    float e1 = __expf(m1 - mM), e2 = __expf(m2 - mM);
    float inv = 1.f / (l1 * e1 + l2 * e2);
    float4 a1 = ((const float4*)g_pacc)[(size_t)r0 * 8 + q4];
    float4 a2 = ((const float4*)g_pacc)[(size_t)(16384 + r0) * 8 + q4];
    float4 o;
    o.x = (a1.x * e1 + a2.x * e2) * inv;
    o.y = (a1.y * e1 + a2.y * e2) * inv;
    o.z = (a1.z * e1 + a2.z * e2) * inv;
    o.w = (a1.w * e1 + a2.w * e2) * inv;
    ((float4*)g_attn)[(((size_t)(b * 1024) + t) * 256 + h * 32) / 4 + q4] = o;
}

// ---------------------------------------------------------------------------
// K5b: up_norm — LN over D; [b][t][d] -> [b][d][t]. Tiled transpose.
// ---------------------------------------------------------------------------
__global__ void k_upnorm() {
    __shared__ __align__(16) float sm[256][33];
    __shared__ float red1[8][32], red2[8][32];
    __shared__ float smu[32], srs[32];
    int tid = threadIdx.x;  // 256
    int b = blockIdx.y;
    int t0 = blockIdx.x * 32;
    for (int i = tid; i < 8192; i += 256) {
        int tt = i >> 8, d = i & 255;
        sm[d][tt] = g_o[((size_t)(b * 1024) + t0 + tt) * 256 + d];
    }
    __syncthreads();
    int col = tid & 31, part = tid >> 5;
    float s1 = 0.f, s2 = 0.f;
    for (int j = 0; j < 32; j++) {
        float v = sm[part * 32 + j][col];
        s1 += v;
        s2 = fmaf(v, v, s2);
    }
    red1[part][col] = s1;
    red2[part][col] = s2;
    __syncthreads();
    if (tid < 32) {
        float a = 0.f, c2 = 0.f;
        for (int p = 0; p < 8; p++) { a += red1[p][tid]; c2 += red2[p][tid]; }
        float mu = a * (1.f / 256.f);
        smu[tid] = mu;
        srs[tid] = rsqrtf(c2 * (1.f / 256.f) - mu * mu + 1e-6f);
    }
    __syncthreads();
    for (int i = tid; i < 8192; i += 256) {
        int d = i >> 5, tt = i & 31;
        g_ln2[(size_t)(b * 256 + d) * 1024 + t0 + tt] = (sm[d][tt] - smu[tt]) * srs[tt];
    }
}

// ---------------------------------------------------------------------------
// K6: recov conv(3,1) + pixel-shuffle + residual -> out (f32x2)
// ---------------------------------------------------------------------------
__global__ void k_recov(const float* __restrict__ x,
                        const float* __restrict__ rw,
                        const float* __restrict__ rb,
                        float* __restrict__ outp) {
    extern __shared__ float sm6[];
    float* ws = sm6;             // [512][24]
    float* bbs = sm6 + 512 * 24;
    int tid = threadIdx.x;
    int b = blockIdx.z, fa = blockIdx.y;
    int t = blockIdx.x * 128 + tid;
    for (int i = tid; i < 3072; i += 128) ((float4*)ws)[i] = ((const float4*)rw)[i];
    for (int i = tid; i < 512; i += 128) bbs[i] = rb[i];
    __syncthreads();

    float xv[24];
#pragma unroll
    for (int i = 0; i < 8; i++) {
#pragma unroll
        for (int kh = 0; kh < 3; kh++) {
            int fs = fa + kh - 1;
            xv[i * 3 + kh] = (fs >= 0 && fs < 32)
                ? g_ln2[((size_t)(b * 256) + i * 32 + fs) * 1024 + t] : 0.f;
        }
    }
    u64t xv2[12];
#pragma unroll
    for (int q = 0; q < 12; q++) xv2[q] = fpk(xv[2 * q], xv[2 * q + 1]);

    for (int o = 0; o < 512; o++) {
        const u64t* wp = (const u64t*)(ws + o * 24);
        u64t aa = 0ull, bb2 = 0ull;
#pragma unroll
        for (int q = 0; q < 12; q += 2) {
            aa = ffma2(xv2[q], wp[q], aa);
            bb2 = ffma2(xv2[q + 1], wp[q + 1], bb2);
        }
        float accv = fsum2(aa) + fsum2(bb2) + bbs[o];
        int cch = o >> 3, r = o & 7;
        size_t idx = ((size_t)(b * 64 + cch) * 256 + fa * 8 + r) * 1024 + t;
        outp[idx] = x[idx] + accv;
    }
}

// ---------------------------------------------------------------------------
// K7: gated MLP, register-tiled fused GEMM pair. block (t128, fg8, b), 256 thr.
// smem: ms[64 rows][8 chunks of 8 u64 + pad] (73 u64/row), hs[128][73],
//       w1t[c][o] 64x260 f32, w2t[k][c] 128x68 f32, biases/mod/stats.
// ---------------------------------------------------------------------------
#define MS_STRIDE 73   // u64 per row (8 chunks * 9)
#define W1T_STRIDE 260
#define W2T_STRIDE 68

__global__ void __launch_bounds__(256)
k_mlp(float* __restrict__ xio,
      const float* __restrict__ fc1w, const float* __restrict__ fc1b,
      const float* __restrict__ fc2w, const float* __restrict__ fc2b) {
    extern __shared__ __align__(16) u64t smbase[];
    u64t* ms = smbase;                       // 64*73 u64
    u64t* hs = ms + 64 * MS_STRIDE;          // 128*73 u64
    float* w1t = (float*)(hs + 128 * MS_STRIDE);   // 64*260
    float* w2t = w1t + 64 * W1T_STRIDE;            // 128*68
    float* b1  = w2t + 128 * W2T_STRIDE;           // 256
    float* b2  = b1 + 256;                         // 64
    float* sh2 = b2 + 64;
    float* sc2 = sh2 + 64;
    float* gg2 = sc2 + 64;
    float* smu = gg2 + 64;                         // 128
    float* srs = smu + 128;                        // 128

    int tid = threadIdx.x;
    int b = blockIdx.z, fg = blockIdx.y;
    int t0 = blockIdx.x * 128;

    // load + transpose weights (once per block)
    for (int i = tid; i < 16384; i += 256) {
        int o = i >> 6, c = i & 63;
        w1t[c * W1T_STRIDE + o] = fc1w[i];
    }
    for (int i = tid; i < 8192; i += 256) {
        int c = i >> 7, k = i & 127;
        w2t[k * W2T_STRIDE + c] = fc2w[i];
    }
    if (tid < 256) b1[tid] = fc1b[tid];
    if (tid < 64) {
        b2[tid]  = fc2b[tid];
        sh2[tid] = g_mlpm[b * 192 + tid];
        sc2[tid] = g_mlpm[b * 192 + 64 + tid];
        gg2[tid] = g_mlpm[b * 192 + 128 + tid];
    }
    __syncthreads();

    int rg = tid >> 3, cg = tid & 7;     // GEMM1: 32 row-groups x 8 col-groups
    int o0 = rg * 4;
    int wrp = tid >> 5, lane = tid & 31; // loader mapping

    for (int fi = 0; fi < 8; fi++) {
        int f = fg * 8 + fi;
        float* xp = xio + ((size_t)(b * 64) * 256 + f) * 1024 + t0;

        // 1. load x tile [64 c][128 t] -> ms (chunked layout)
        {
#pragma unroll
            for (int r = 0; r < 8; r++) {
                int c = wrp * 8 + r;
                float4 v = *(const float4*)(xp + (size_t)c * 262144 + lane * 4);
                int tp = lane * 2;
                u64t* dst = ms + c * MS_STRIDE + (tp >> 3) * 9 + (tp & 7);
                dst[0] = fpk(v.x, v.y);
                dst[1] = fpk(v.z, v.w);
            }
        }
        __syncthreads();

        // 2. per-t stats (2 threads per t)
        {
            int t = tid >> 1, half = tid & 1;
            const float* msf = (const float*)ms;
            int ta = (9 * (t >> 4) + ((t >> 1) & 7)) * 2 + (t & 1);
            float s1 = 0.f, s2 = 0.f;
            int c0 = half * 32;
#pragma unroll 8
            for (int c = c0; c < c0 + 32; c++) {
                float v = msf[c * (2 * MS_STRIDE) + ta];
                s1 += v;
                s2 = fmaf(v, v, s2);
            }
            s1 += __shfl_xor_sync(0xffffffffu, s1, 1);
            s2 += __shfl_xor_sync(0xffffffffu, s2, 1);
            if (!half) {
                float mu = s1 * (1.f / 64.f);
                smu[t] = mu;
                srs[t] = rsqrtf(s2 * (1.f / 64.f) - mu * mu + 1e-6f);
            }
        }
        __syncthreads();

        // 3. normalize + modulate in place
        {
            int t = tid >> 1, half = tid & 1;
            float* msf = (float*)ms;
            int ta = (9 * (t >> 4) + ((t >> 1) & 7)) * 2 + (t & 1);
            float mu = smu[t], rs = srs[t];
            int c0 = half * 32;
#pragma unroll 8
            for (int c = c0; c < c0 + 32; c++) {
                float v = msf[c * (2 * MS_STRIDE) + ta];
                msf[c * (2 * MS_STRIDE) + ta] = (v - mu) * rs * (1.f + sc2[c]) + sh2[c];
            }
        }
        __syncthreads();

        // 4. GEMM1: C1[o=256][tp=64] ; thread: rows {o0..o0+3, o0+128..+131} x 8 tp
        u64t acc[8][8];
#pragma unroll
        for (int i = 0; i < 8; i++)
#pragma unroll
            for (int j = 0; j < 8; j++) acc[i][j] = 0ull;

        for (int k = 0; k < 64; k++) {
            const float* wr = w1t + k * W1T_STRIDE + o0;
            float4 wu = *(const float4*)wr;
            float4 wg = *(const float4*)(wr + 128);
            u64t wu2[4] = {fpk(wu.x, wu.x), fpk(wu.y, wu.y), fpk(wu.z, wu.z), fpk(wu.w, wu.w)};
            u64t wg2[4] = {fpk(wg.x, wg.x), fpk(wg.y, wg.y), fpk(wg.z, wg.z), fpk(wg.w, wg.w)};
            const u64t* mrow = ms + k * MS_STRIDE + cg * 9;
            u64t mv[8];
#pragma unroll
            for (int j = 0; j < 8; j++) mv[j] = mrow[j];
#pragma unroll
            for (int i = 0; i < 4; i++)
#pragma unroll
                for (int j = 0; j < 8; j++) {
                    acc[i][j]     = ffma2(wu2[i], mv[j], acc[i][j]);
                    acc[4 + i][j] = ffma2(wg2[i], mv[j], acc[4 + i][j]);
                }
        }

        // 5. GLU (thread-local: u row o0+i pairs with g row o0+128+i) -> hs
#pragma unroll
        for (int i = 0; i < 4; i++) {
            float bu = b1[o0 + i], bg = b1[o0 + 128 + i];
            u64t* hrow = hs + (o0 + i) * MS_STRIDE + cg * 9;
#pragma unroll
            for (int j = 0; j < 8; j++) {
                float u0, u1, g0, g1;
                fupk(acc[i][j], u0, u1);
                fupk(acc[4 + i][j], g0, g1);
                u0 += bu; u1 += bu; g0 += bg; g1 += bg;
                float h0 = u0 * __fdividef(g0, 1.f + __expf(-g0));
                float h1 = u1 * __fdividef(g1, 1.f + __expf(-g1));
                hrow[j] = fpk(h0, h1);
            }
        }
        __syncthreads();

        // 6. GEMM2 + epilogue (threads < 128): thread: 4 c x 8 tp
        if (tid < 128) {
            int c0 = (tid >> 3) * 4, tq = tid & 7;
            u64t a2[4][8];
#pragma unroll
            for (int ci = 0; ci < 4; ci++)
#pragma unroll
                for (int j = 0; j < 8; j++) a2[ci][j] = 0ull;

            for (int k = 0; k < 128; k++) {
                float4 wv = *(const float4*)(w2t + k * W2T_STRIDE + c0);
                u64t w2v[4] = {fpk(wv.x, wv.x), fpk(wv.y, wv.y), fpk(wv.z, wv.z), fpk(wv.w, wv.w)};
                const u64t* hrow = hs + k * MS_STRIDE + tq * 9;
                u64t hv[8];
#pragma unroll
                for (int j = 0; j < 8; j++) hv[j] = hrow[j];
#pragma unroll
                for (int ci = 0; ci < 4; ci++)
#pragma unroll
                    for (int j = 0; j < 8; j++)
                        a2[ci][j] = ffma2(w2v[ci], hv[j], a2[ci][j]);
            }
#pragma unroll
            for (int ci = 0; ci < 4; ci++) {
                int c = c0 + ci;
                float gg = gg2[c], bb = b2[c];
                float* row = xp + (size_t)c * 262144;
#pragma unroll
                for (int j = 0; j < 8; j++) {
                    int tt = (tq * 8 + j) * 2;
                    float2 xv = *(float2*)(row + tt);
                    float a0, a1;
                    fupk(a2[ci][j], a0, a1);
                    xv.x += gg * (a0 + bb);
                    xv.y += gg * (a1 + bb);
                    *(float2*)(row + tt) = xv;
                }
            }
        }
        // no sync needed: next-iter writes touch ms only (not read by GEMM2),
        // and two barriers separate GEMM2's hs reads from the next hs writes.
    }
}

// ---------------------------------------------------------------------------
extern "C" void kernel_launch(void* const* d_in, const int* in_sizes, int n_in,
                              void* d_out, int out_size) {
    const float* x         = (const float*)d_in[0];
    const float* c         = (const float*)d_in[1];
    const float* sup_w     = (const float*)d_in[2];
    const float* sup_b     = (const float*)d_in[3];
    const float* qkv_w     = (const float*)d_in[4];
    const float* qkv_b     = (const float*)d_in[5];
    const float* out_w     = (const float*)d_in[6];
    const float* out_b     = (const float*)d_in[7];
    const float* recov_w   = (const float*)d_in[8];
    const float* recov_b   = (const float*)d_in[9];
    const float* ada_att_w = (const float*)d_in[10];
    const float* ada_att_b = (const float*)d_in[11];
    const float* ada_mlp_w = (const float*)d_in[12];
    const float* ada_mlp_b = (const float*)d_in[13];
    const float* fc1_w     = (const float*)d_in[14];
    const float* fc1_b     = (const float*)d_in[15];
    const float* fc2_w     = (const float*)d_in[16];
    const float* fc2_b     = (const float*)d_in[17];
    float* outp = (float*)d_out;

    // smem: (64+128)*73 u64 = 112128 B ; floats: 16640+8704+256+4*64+256 = 26112 f
    const int MLP_SMEM = (64 + 128) * MS_STRIDE * 8 +
                         (64 * W1T_STRIDE + 128 * W2T_STRIDE + 256 + 64 * 4 + 256) * 4;
    cudaFuncSetAttribute(k_recov, cudaFuncAttributeMaxDynamicSharedMemorySize, 51200);
    cudaFuncSetAttribute(k_mlp,   cudaFuncAttributeMaxDynamicSharedMemorySize, MLP_SMEM);

    float *p_xt, *p_qkv, *p_attn, *p_o, *p_attm;
    cudaGetSymbolAddress((void**)&p_xt,   g_xt);
    cudaGetSymbolAddress((void**)&p_qkv,  g_qkv);
    cudaGetSymbolAddress((void**)&p_attn, g_attn);
    cudaGetSymbolAddress((void**)&p_o,    g_o);
    cudaGetSymbolAddress((void**)&p_attm, g_attm);

    k_ada<<<240, 256>>>(c, ada_att_w, ada_att_b, ada_mlp_w, ada_mlp_b);
    k_ropetab<<<64, 256>>>();
    k_sup<<<dim3(8, 32, 2), 128>>>(x, sup_w, sup_b);
    k_ln_mod<<<dim3(32, 2), 256>>>();
    k_gemm64<<<dim3(12, 32), 256>>>(p_xt, qkv_w, qkv_b, p_qkv, 768, 256, nullptr, 1);
    k_attn2<<<dim3(8, 8, 4), 128>>>();
    k_attn_comb<<<512, 256>>>();
    k_gemm64<<<dim3(4, 32), 256>>>(p_attn, out_w, out_b, p_o, 256, 256, p_attm + 512, 0);
    k_upnorm<<<dim3(32, 2), 256>>>();
    k_recov<<<dim3(8, 32, 2), 128, 51200>>>(x, recov_w, recov_b, outp);
    k_mlp<<<dim3(8, 32, 2), 256, MLP_SMEM>>>(outp, fc1_w, fc1_b, fc2_w, fc2_b);
}

// round 9
// speedup vs baseline: 3.9120x; 1.4709x over previous
#include <cuda_runtime.h>
#include <cuda_bf16.h>
#include <mma.h>
#include <math.h>

using namespace nvcuda;

// ---------------------------------------------------------------------------
// FullTimeAtt: B=2, C=64, F=256, T=1024, R=8, SUP=8, Fatt=32, D=256, H=8, hd=32
// fp32 f32x2 pipeline; MLP on WMMA bf16 (HMMA — supported on base sm_100).
// ---------------------------------------------------------------------------

typedef unsigned long long u64t;

__device__ __forceinline__ u64t ffma2(u64t a, u64t b, u64t c) {
    u64t d;
    asm("fma.rn.f32x2 %0, %1, %2, %3;" : "=l"(d) : "l"(a), "l"(b), "l"(c));
    return d;
}
__device__ __forceinline__ u64t fmul2(u64t a, u64t b) {
    u64t d;
    asm("mul.rn.f32x2 %0, %1, %2;" : "=l"(d) : "l"(a), "l"(b));
    return d;
}
__device__ __forceinline__ u64t fpk(float lo, float hi) {
    u64t r;
    asm("mov.b64 %0, {%1, %2};" : "=l"(r) : "f"(lo), "f"(hi));
    return r;
}
__device__ __forceinline__ void fupk(u64t v, float& a, float& b) {
    asm("mov.b64 {%0, %1}, %2;" : "=f"(a), "=f"(b) : "l"(v));
}
__device__ __forceinline__ float fsum2(u64t v) {
    float a, b;
    fupk(v, a, b);
    return a + b;
}
__device__ __forceinline__ unsigned bfpack(float lo, float hi) {
    unsigned r;
    asm("cvt.rn.bf16x2.f32 %0, %1, %2;" : "=r"(r) : "f"(hi), "f"(lo));
    return r;
}

__device__ float g_attm[2 * 768];
__device__ float g_mlpm[2 * 192];
__device__ float g_cos[1024 * 16];
__device__ float g_sin[1024 * 16];
__device__ float g_xf  [2 * 256 * 1024];
__device__ float g_xt  [2 * 1024 * 256];
__device__ float g_qkv [2 * 1024 * 768];
__device__ float g_attn[2 * 1024 * 256];
__device__ float g_o   [2 * 1024 * 256];
__device__ float g_ln2 [2 * 256 * 1024];
__device__ float g_pacc[2 * 2 * 8 * 1024 * 32];
__device__ float g_pml [2 * 2 * 8 * 1024 * 2];

// ---------------------------------------------------------------------------
__global__ void k_ada(const float* __restrict__ c,
                      const float* __restrict__ aw, const float* __restrict__ ab,
                      const float* __restrict__ mw, const float* __restrict__ mb) {
    int wid = (blockIdx.x * blockDim.x + threadIdx.x) >> 5;
    int lane = threadIdx.x & 31;
    if (wid >= 1920) return;
    const float* w;
    const float* bia;
    float* dst;
    int b, o;
    if (wid < 1536) {
        b = wid / 768; o = wid % 768;
        w = aw + (size_t)o * 512; bia = ab; dst = g_attm + wid;
    } else {
        int i = wid - 1536;
        b = i / 192; o = i % 192;
        w = mw + (size_t)o * 512; bia = mb; dst = g_mlpm + i;
    }
    const float* cb = c + b * 512;
    float acc = 0.f;
    for (int k = lane; k < 512; k += 32) {
        float v = cb[k];
        float s = v / (1.f + __expf(-v));
        acc = fmaf(s, w[k], acc);
    }
#pragma unroll
    for (int off = 16; off; off >>= 1) acc += __shfl_xor_sync(0xffffffffu, acc, off);
    if (lane == 0) dst[0] = acc + bia[o];
}

__global__ void k_ropetab() {
    int idx = blockIdx.x * 256 + threadIdx.x;
    int t = idx >> 4, j = idx & 15;
    float inv = (float)(1.0 / pow(10000.0, (double)(2 * j) / 32.0));
    float ang = (float)t * inv;
    float s, cc;
    sincosf(ang, &s, &cc);
    g_cos[idx] = cc;
    g_sin[idx] = s;
}

// ---------------------------------------------------------------------------
__global__ void k_sup(const float* __restrict__ x,
                      const float* __restrict__ sup_w,
                      const float* __restrict__ sup_b) {
    __shared__ __align__(16) float wt[512 * 16];
    __shared__ float bs[16];
    int tid = threadIdx.x;
    int b = blockIdx.z, fa = blockIdx.y;
    int t = blockIdx.x * 128 + tid;
    for (int i = tid; i < 512 * 16; i += 128) {
        int o = i >> 9, cr = i & 511;
        wt[cr * 16 + o] = sup_w[i];
    }
    if (tid < 16) bs[tid] = sup_b[tid];
    __syncthreads();

    const float* xb = x + ((size_t)(b * 64) * 256 + fa * 8) * 1024 + t;

    float s1[8], s2[8];
#pragma unroll
    for (int r = 0; r < 8; r++) { s1[r] = 0.f; s2[r] = 0.f; }
    for (int cch = 0; cch < 64; cch++) {
#pragma unroll
        for (int r = 0; r < 8; r++) {
            float v = xb[(size_t)(cch * 256 + r) * 1024];
            s1[r] += v;
            s2[r] = fmaf(v, v, s2[r]);
        }
    }
    float mu[8], rs[8];
#pragma unroll
    for (int r = 0; r < 8; r++) {
        mu[r] = s1[r] * (1.f / 64.f);
        float var = s2[r] * (1.f / 64.f) - mu[r] * mu[r];
        rs[r] = rsqrtf(var + 1e-6f);
    }

    u64t acc2[8];
#pragma unroll
    for (int q = 0; q < 8; q++) acc2[q] = 0ull;
    for (int cch = 0; cch < 64; cch++) {
#pragma unroll
        for (int r = 0; r < 8; r++) {
            float xn = (xb[(size_t)(cch * 256 + r) * 1024] - mu[r]) * rs[r];
            u64t x2 = fpk(xn, xn);
            const u64t* wp = (const u64t*)(wt + (cch * 8 + r) * 16);
#pragma unroll
            for (int q = 0; q < 8; q++) acc2[q] = ffma2(x2, wp[q], acc2[q]);
        }
    }
    float accv[16];
#pragma unroll
    for (int q = 0; q < 8; q++) fupk(acc2[q], accv[2 * q], accv[2 * q + 1]);
#pragma unroll
    for (int s = 0; s < 8; s++) {
        float ya = accv[s] + bs[s];
        float yb = accv[s + 8] + bs[s + 8];
        float outv = ya * (yb / (1.f + __expf(-yb)));
        g_xf[((size_t)(b * 256) + (s * 32 + fa)) * 1024 + t] = outv;
    }
}

// ---------------------------------------------------------------------------
__global__ void k_ln_mod() {
    __shared__ __align__(16) float sm[256][33];
    __shared__ float shs[256], scs[256];
    __shared__ float red1[8][32], red2[8][32];
    __shared__ float smu[32], srs[32];
    int tid = threadIdx.x;
    int b = blockIdx.y;
    int t0 = blockIdx.x * 32;
    for (int i = tid; i < 256; i += 256) {
        shs[i] = g_attm[b * 768 + i];
        scs[i] = 1.f + g_attm[b * 768 + 256 + i];
    }
    for (int i = tid; i < 8192; i += 256) {
        int d = i >> 5, tt = i & 31;
        sm[d][tt] = g_xf[(size_t)(b * 256 + d) * 1024 + t0 + tt];
    }
    __syncthreads();
    int col = tid & 31, part = tid >> 5;
    float s1 = 0.f, s2 = 0.f;
    for (int j = 0; j < 32; j++) {
        float v = sm[part * 32 + j][col];
        s1 += v;
        s2 = fmaf(v, v, s2);
    }
    red1[part][col] = s1;
    red2[part][col] = s2;
    __syncthreads();
    if (tid < 32) {
        float a = 0.f, c2 = 0.f;
        for (int p = 0; p < 8; p++) { a += red1[p][tid]; c2 += red2[p][tid]; }
        float mu = a * (1.f / 256.f);
        smu[tid] = mu;
        srs[tid] = rsqrtf(c2 * (1.f / 256.f) - mu * mu + 1e-6f);
    }
    __syncthreads();
    for (int i = tid; i < 8192; i += 256) {
        int tt = i >> 8, d = i & 255;
        float v = (sm[d][tt] - smu[tt]) * srs[tt] * scs[d] + shs[d];
        g_xt[((size_t)(b * 1024) + t0 + tt) * 256 + d] = v;
    }
}

// ---------------------------------------------------------------------------
__global__ void k_gemm64(const float* __restrict__ A, const float* __restrict__ W,
                         const float* __restrict__ bias, float* __restrict__ C,
                         int N, int K, const float* __restrict__ gate, int rope) {
    __shared__ __align__(16) float As[64][17];
    __shared__ __align__(16) float Wst[16][66];
    int tid = threadIdx.x;
    int row0 = blockIdx.y * 64, col0 = blockIdx.x * 64;
    int ty = tid >> 4, tx = tid & 15;
    int lr = tid >> 2, lk = (tid & 3) * 4;
    u64t acc2[4][2];
#pragma unroll
    for (int i = 0; i < 4; i++) { acc2[i][0] = 0ull; acc2[i][1] = 0ull; }

    for (int k0 = 0; k0 < K; k0 += 16) {
        float4 av = *(const float4*)(A + (size_t)(row0 + lr) * K + k0 + lk);
        float4 wv = *(const float4*)(W + (size_t)(col0 + lr) * K + k0 + lk);
        __syncthreads();
        As[lr][lk + 0] = av.x; As[lr][lk + 1] = av.y; As[lr][lk + 2] = av.z; As[lr][lk + 3] = av.w;
        Wst[lk + 0][lr] = wv.x; Wst[lk + 1][lr] = wv.y; Wst[lk + 2][lr] = wv.z; Wst[lk + 3][lr] = wv.w;
        __syncthreads();
#pragma unroll
        for (int kk = 0; kk < 16; kk++) {
            const u64t* wr = (const u64t*)(&Wst[kk][0]);
            u64t b0 = wr[tx * 2], b1 = wr[tx * 2 + 1];
#pragma unroll
            for (int i = 0; i < 4; i++) {
                float a = As[ty * 4 + i][kk];
                u64t a2 = fpk(a, a);
                acc2[i][0] = ffma2(a2, b0, acc2[i][0]);
                acc2[i][1] = ffma2(a2, b1, acc2[i][1]);
            }
        }
    }
#pragma unroll
    for (int i = 0; i < 4; i++) {
        int r = row0 + ty * 4 + i;
        int t = r & 1023;
#pragma unroll
        for (int p = 0; p < 2; p++) {
            float v0, v1;
            fupk(acc2[i][p], v0, v1);
            int cc = col0 + tx * 4 + p * 2;
            v0 += bias[cc];
            v1 += bias[cc + 1];
            if (rope && cc < 512) {
                int j = (cc & 31) >> 1;
                float co = g_cos[t * 16 + j], si = g_sin[t * 16 + j];
                float r0 = v0 * co - v1 * si;
                float r1 = v0 * si + v1 * co;
                v0 = r0; v1 = r1;
            }
            if (gate) {
                v0 *= gate[(r >> 10) * 768 + cc];
                v1 *= gate[(r >> 10) * 768 + cc + 1];
            }
            float2 st; st.x = v0; st.y = v1;
            *(float2*)(C + (size_t)r * N + cc) = st;
        }
    }
}

// ---------------------------------------------------------------------------
__global__ void k_attn2() {
    __shared__ __align__(16) float ks[32][32];
    __shared__ __align__(16) float vs[32][32];
    int tid = threadIdx.x;
    int z = blockIdx.z;
    int b = z >> 1, sp = z & 1;
    int h = blockIdx.y;
    int t = blockIdx.x * 128 + tid;
    const float* qp = g_qkv + ((size_t)(b * 1024) + t) * 768 + h * 32;
    u64t q2[16];
    const u64t* qq = (const u64t*)qp;
#pragma unroll
    for (int i = 0; i < 16; i++) q2[i] = qq[i];
    float m = -1e30f, l = 0.f;
    u64t acc2[16];
#pragma unroll
    for (int i = 0; i < 16; i++) acc2[i] = 0ull;
    const float scale = 0.17677669529663689f;

    int s_begin = sp * 512;
    for (int st0 = s_begin; st0 < s_begin + 512; st0 += 32) {
        __syncthreads();
        for (int i = tid; i < 256; i += 128) {
            int rr = i >> 3, c4 = (i & 7) * 4;
            const float* kb = g_qkv + ((size_t)(b * 1024) + st0 + rr) * 768 + 256 + h * 32 + c4;
            *(float4*)(&ks[rr][c4]) = *(const float4*)kb;
            *(float4*)(&vs[rr][c4]) = *(const float4*)(kb + 256);
        }
        __syncthreads();
        float scl[32];
        float tmax = -1e30f;
#pragma unroll
        for (int s = 0; s < 32; s++) {
            const u64t* kr = (const u64t*)(&ks[s][0]);
            u64t da = 0ull, db = 0ull;
#pragma unroll
            for (int q = 0; q < 16; q += 2) {
                da = ffma2(q2[q], kr[q], da);
                db = ffma2(q2[q + 1], kr[q + 1], db);
            }
            float dot = (fsum2(da) + fsum2(db)) * scale;
            scl[s] = dot;
            tmax = fmaxf(tmax, dot);
        }
        float mn = fmaxf(m, tmax);
        float corr = __expf(m - mn);
        l *= corr;
        u64t c2 = fpk(corr, corr);
#pragma unroll
        for (int i = 0; i < 16; i++) acc2[i] = fmul2(acc2[i], c2);
#pragma unroll
        for (int s = 0; s < 32; s++) {
            float p = __expf(scl[s] - mn);
            l += p;
            u64t p2 = fpk(p, p);
            const u64t* vr = (const u64t*)(&vs[s][0]);
#pragma unroll
            for (int i = 0; i < 16; i++) acc2[i] = ffma2(p2, vr[i], acc2[i]);
        }
        m = mn;
    }
    int r0 = sp * 16384 + (b * 8 + h) * 1024 + t;
    g_pml[r0 * 2] = m;
    g_pml[r0 * 2 + 1] = l;
    float* op = g_pacc + (size_t)r0 * 32;
#pragma unroll
    for (int i = 0; i < 16; i += 2) {
        float4 o;
        fupk(acc2[i], o.x, o.y);
        fupk(acc2[i + 1], o.z, o.w);
        *(float4*)(op + 2 * i) = o;
    }
}

__global__ void k_attn_comb() {
    int idx = blockIdx.x * 256 + threadIdx.x;
    int row = idx >> 3, q4 = idx & 7;
    int b = row >> 13, rem = row & 8191;
    int h = rem >> 10, t = rem & 1023;
    int r0 = (b * 8 + h) * 1024 + t;
    float m1 = g_pml[r0 * 2], l1 = g_pml[r0 * 2 + 1];
    float m2 = g_pml[(16384 + r0) * 2], l2 = g_pml[(16384 + r0) * 2 + 1];
    float mM = fmaxf(m1, m2);
    float e1 = __expf(m1 - mM), e2 = __expf(m2 - mM);
    float inv = 1.f / (l1 * e1 + l2 * e2);
    float4 a1 = ((const float4*)g_pacc)[(size_t)r0 * 8 + q4];
    float4 a2 = ((const float4*)g_pacc)[(size_t)(16384 + r0) * 8 + q4];
    float4 o;
    o.x = (a1.x * e1 + a2.x * e2) * inv;
    o.y = (a1.y * e1 + a2.y * e2) * inv;
    o.z = (a1.z * e1 + a2.z * e2) * inv;
    o.w = (a1.w * e1 + a2.w * e2) * inv;
    ((float4*)g_attn)[(((size_t)(b * 1024) + t) * 256 + h * 32) / 4 + q4] = o;
}

// ---------------------------------------------------------------------------
__global__ void k_upnorm() {
    __shared__ __align__(16) float sm[256][33];
    __shared__ float red1[8][32], red2[8][32];
    __shared__ float smu[32], srs[32];
    int tid = threadIdx.x;
    int b = blockIdx.y;
    int t0 = blockIdx.x * 32;
    for (int i = tid; i < 8192; i += 256) {
        int tt = i >> 8, d = i & 255;
        sm[d][tt] = g_o[((size_t)(b * 1024) + t0 + tt) * 256 + d];
    }
    __syncthreads();
    int col = tid & 31, part = tid >> 5;
    float s1 = 0.f, s2 = 0.f;
    for (int j = 0; j < 32; j++) {
        float v = sm[part * 32 + j][col];
        s1 += v;
        s2 = fmaf(v, v, s2);
    }
    red1[part][col] = s1;
    red2[part][col] = s2;
    __syncthreads();
    if (tid < 32) {
        float a = 0.f, c2 = 0.f;
        for (int p = 0; p < 8; p++) { a += red1[p][tid]; c2 += red2[p][tid]; }
        float mu = a * (1.f / 256.f);
        smu[tid] = mu;
        srs[tid] = rsqrtf(c2 * (1.f / 256.f) - mu * mu + 1e-6f);
    }
    __syncthreads();
    for (int i = tid; i < 8192; i += 256) {
        int d = i >> 5, tt = i & 31;
        g_ln2[(size_t)(b * 256 + d) * 1024 + t0 + tt] = (sm[d][tt] - smu[tt]) * srs[tt];
    }
}

// ---------------------------------------------------------------------------
__global__ void k_recov(const float* __restrict__ x,
                        const float* __restrict__ rw,
                        const float* __restrict__ rb,
                        float* __restrict__ outp) {
    extern __shared__ float sm6[];
    float* ws = sm6;
    float* bbs = sm6 + 512 * 24;
    int tid = threadIdx.x;
    int b = blockIdx.z, fa = blockIdx.y;
    int t = blockIdx.x * 128 + tid;
    for (int i = tid; i < 3072; i += 128) ((float4*)ws)[i] = ((const float4*)rw)[i];
    for (int i = tid; i < 512; i += 128) bbs[i] = rb[i];
    __syncthreads();

    float xv[24];
#pragma unroll
    for (int i = 0; i < 8; i++) {
#pragma unroll
        for (int kh = 0; kh < 3; kh++) {
            int fs = fa + kh - 1;
            xv[i * 3 + kh] = (fs >= 0 && fs < 32)
                ? g_ln2[((size_t)(b * 256) + i * 32 + fs) * 1024 + t] : 0.f;
        }
    }
    u64t xv2[12];
#pragma unroll
    for (int q = 0; q < 12; q++) xv2[q] = fpk(xv[2 * q], xv[2 * q + 1]);

    for (int o = 0; o < 512; o++) {
        const u64t* wp = (const u64t*)(ws + o * 24);
        u64t aa = 0ull, bb2 = 0ull;
#pragma unroll
        for (int q = 0; q < 12; q += 2) {
            aa = ffma2(xv2[q], wp[q], aa);
            bb2 = ffma2(xv2[q + 1], wp[q + 1], bb2);
        }
        float accv = fsum2(aa) + fsum2(bb2) + bbs[o];
        int cch = o >> 3, r = o & 7;
        size_t idx = ((size_t)(b * 64 + cch) * 256 + fa * 8 + r) * 1024 + t;
        outp[idx] = x[idx] + accv;
    }
}

// ---------------------------------------------------------------------------
// K7: gated MLP via WMMA bf16 (HMMA, base sm_100).
// Block = (ttile16 x 64pos, fgroup 32, b 2), 256 threads (8 warps), 8 f-iters.
// Per f-iter:
//   LN+modulate -> Abf[64][72] bf16
//   GEMM1: [64x64]@W1^T -> u,g accum fragments (bias via replicated-acc init)
//   GLU elementwise on fragments -> Hf f32 -> Hbf[64][136] bf16
//   GEMM2: [64x128]@W2^T -> C2[64][72] f32 (bias2 via acc init)
//   epilogue: out += g2[c]*C2
// smem offsets (bytes, all 16B-aligned):
#define W1BF_OFF  0u        // bf16 [256][72]  = 36864
#define W2BF_OFF  36864u    // bf16 [64][136]  = 17408
#define BREP_OFF  54272u    // f32 [16][264]   = 16896 (fc1b replicated)
#define B2REP_OFF 71168u    // f32 [16][72]    = 4608  (fc2b replicated)
#define ABF_OFF   75776u    // bf16 [64][72]   = 9216
#define HF_OFF    84992u    // f32 [64][136]   = 34816 (aliased: xs f32 [64][72])
#define HBF_OFF   119808u   // bf16 [64][136]  = 17408
#define C2_OFF    137216u   // f32 [64][72]    = 18432
#define G2_OFF    155648u
#define SH2_OFF   155904u
#define SC2_OFF   156160u
#define SMU_OFF   156416u
#define SRS_OFF   156672u
#define MLPW_SMEM 156928

__global__ void __launch_bounds__(256)
k_mlp(float* __restrict__ xio,
      const float* __restrict__ fc1w, const float* __restrict__ fc1b,
      const float* __restrict__ fc2w, const float* __restrict__ fc2b) {
    extern __shared__ __align__(16) unsigned char smw[];
    __nv_bfloat16* W1bf = (__nv_bfloat16*)(smw + W1BF_OFF);
    __nv_bfloat16* W2bf = (__nv_bfloat16*)(smw + W2BF_OFF);
    float* brep  = (float*)(smw + BREP_OFF);
    float* b2rep = (float*)(smw + B2REP_OFF);
    __nv_bfloat16* Abf = (__nv_bfloat16*)(smw + ABF_OFF);
    float* Hf = (float*)(smw + HF_OFF);
    float* xs = Hf;                      // alias: xs dead before Hf written
    __nv_bfloat16* Hbf = (__nv_bfloat16*)(smw + HBF_OFF);
    float* C2  = (float*)(smw + C2_OFF);
    float* g2s = (float*)(smw + G2_OFF);
    float* sh2 = (float*)(smw + SH2_OFF);
    float* sc2 = (float*)(smw + SC2_OFF);
    float* smu = (float*)(smw + SMU_OFF);
    float* srs = (float*)(smw + SRS_OFF);

    int tid = threadIdx.x;
    int wid = tid >> 5;
    int b = blockIdx.z, fg = blockIdx.y;
    int t0 = blockIdx.x * 64;

    // --- weights/biases once per block ---
    unsigned* W1u = (unsigned*)W1bf;
    for (int i = tid; i < 8192; i += 256) {
        int o = i >> 5, p = i & 31;
        W1u[o * 36 + p] = bfpack(fc1w[o * 64 + 2 * p], fc1w[o * 64 + 2 * p + 1]);
    }
    unsigned* W2u = (unsigned*)W2bf;
    for (int i = tid; i < 4096; i += 256) {
        int o = i >> 6, p = i & 63;
        W2u[o * 68 + p] = bfpack(fc2w[o * 128 + 2 * p], fc2w[o * 128 + 2 * p + 1]);
    }
    for (int i = tid; i < 4096; i += 256) {       // brep[16][264]
        int r = i >> 8, cc = i & 255;
        brep[r * 264 + cc] = fc1b[cc];
    }
    for (int i = tid; i < 1024; i += 256) {       // b2rep[16][72]
        int r = i >> 6, cc = i & 63;
        b2rep[r * 72 + cc] = fc2b[cc];
    }
    if (tid < 64) {
        sh2[tid] = g_mlpm[b * 192 + tid];
        sc2[tid] = g_mlpm[b * 192 + 64 + tid];
        g2s[tid] = g_mlpm[b * 192 + 128 + tid];
    }
    __syncthreads();

    for (int fi = 0; fi < 8; fi++) {
        int f = fg * 8 + fi;
        float* xp = xio + ((size_t)(b * 64) * 256 + f) * 1024 + t0;

        // 1. load x tile [64 c][64 t] -> xs[t][c] (f32, ld 72)
#pragma unroll
        for (int q = 0; q < 16; q++) {
            int i = q * 256 + tid;
            int cch = i >> 6, t = i & 63;
            xs[t * 72 + cch] = xp[(size_t)cch * 262144 + t];
        }
        __syncthreads();

        // 2. per-position LN stats: 4 threads / position
        {
            int pos = tid >> 2, quad = tid & 3;
            const float* row = xs + pos * 72 + quad * 16;
            float s1 = 0.f, s2 = 0.f;
#pragma unroll
            for (int cch = 0; cch < 16; cch++) {
                float v = row[cch];
                s1 += v;
                s2 = fmaf(v, v, s2);
            }
            s1 += __shfl_xor_sync(0xffffffffu, s1, 1);
            s2 += __shfl_xor_sync(0xffffffffu, s2, 1);
            s1 += __shfl_xor_sync(0xffffffffu, s1, 2);
            s2 += __shfl_xor_sync(0xffffffffu, s2, 2);
            if (quad == 0) {
                float mu = s1 * (1.f / 64.f);
                smu[pos] = mu;
                srs[pos] = rsqrtf(s2 * (1.f / 64.f) - mu * mu + 1e-6f);
            }
        }
        __syncthreads();

        // 3. normalize + modulate -> Abf[pos][ch] bf16 (ld 72)
        {
            unsigned* Au = (unsigned*)Abf;
#pragma unroll
            for (int q = 0; q < 8; q++) {
                int i = q * 256 + tid;
                int pos = i >> 5, p = i & 31;
                float mu = smu[pos], rs = srs[pos];
                float a0 = (xs[pos * 72 + 2 * p]     - mu) * rs * (1.f + sc2[2 * p])     + sh2[2 * p];
                float a1 = (xs[pos * 72 + 2 * p + 1] - mu) * rs * (1.f + sc2[2 * p + 1]) + sh2[2 * p + 1];
                Au[pos * 36 + p] = bfpack(a0, a1);
            }
        }
        __syncthreads();

        // 4. GEMM1 + fragment GLU -> Hf (f32, ld 136)
        {
            wmma::fragment<wmma::matrix_a, 16, 16, 16, __nv_bfloat16, wmma::row_major> afr;
            wmma::fragment<wmma::matrix_b, 16, 16, 16, __nv_bfloat16, wmma::col_major> bu, bg;
            wmma::fragment<wmma::accumulator, 16, 16, 16, float> cu, cg;
            int m0 = (wid >> 1) * 16;
#pragma unroll
            for (int j = 0; j < 4; j++) {
                int nU = ((wid & 1) * 4 + j) * 16;   // u-output col base (0..112)
                wmma::load_matrix_sync(cu, brep + nU, 264, wmma::mem_row_major);
                wmma::load_matrix_sync(cg, brep + 128 + nU, 264, wmma::mem_row_major);
#pragma unroll
                for (int k = 0; k < 4; k++) {
                    wmma::load_matrix_sync(afr, Abf + m0 * 72 + k * 16, 72);
                    wmma::load_matrix_sync(bu, W1bf + nU * 72 + k * 16, 72);
                    wmma::load_matrix_sync(bg, W1bf + (size_t)(128 + nU) * 72 + k * 16, 72);
                    wmma::mma_sync(cu, afr, bu, cu);
                    wmma::mma_sync(cg, afr, bg, cg);
                }
#pragma unroll
                for (int e = 0; e < cu.num_elements; e++) {
                    float g = cg.x[e];
                    cu.x[e] = cu.x[e] * __fdividef(g, 1.f + __expf(-g));
                }
                wmma::store_matrix_sync(Hf + m0 * 136 + nU, cu, 136, wmma::mem_row_major);
            }
        }
        __syncthreads();

        // 5. pack Hf f32 -> Hbf bf16 (ld 136)
        {
            unsigned* Hu = (unsigned*)Hbf;
#pragma unroll
            for (int q = 0; q < 16; q++) {
                int i = q * 256 + tid;
                int pos = i >> 6, p = i & 63;
                Hu[pos * 68 + p] = bfpack(Hf[pos * 136 + 2 * p], Hf[pos * 136 + 2 * p + 1]);
            }
        }
        __syncthreads();

        // 6. GEMM2: C2[64][64] = Hbf @ W2^T (bias2 via acc init), ld 72
        {
            wmma::fragment<wmma::matrix_a, 16, 16, 16, __nv_bfloat16, wmma::row_major> afr;
            wmma::fragment<wmma::matrix_b, 16, 16, 16, __nv_bfloat16, wmma::col_major> bfr;
            wmma::fragment<wmma::accumulator, 16, 16, 16, float> acc;
#pragma unroll
            for (int s = 0; s < 2; s++) {
                int idx = wid * 2 + s;
                int m0 = (idx >> 2) * 16, n0 = (idx & 3) * 16;
                wmma::load_matrix_sync(acc, b2rep + n0, 72, wmma::mem_row_major);
#pragma unroll
                for (int k = 0; k < 8; k++) {
                    wmma::load_matrix_sync(afr, Hbf + m0 * 136 + k * 16, 136);
                    wmma::load_matrix_sync(bfr, W2bf + n0 * 136 + k * 16, 136);
                    wmma::mma_sync(acc, afr, bfr, acc);
                }
                wmma::store_matrix_sync(C2 + m0 * 72 + n0, acc, 72, wmma::mem_row_major);
            }
        }
        __syncthreads();

        // 7. epilogue: out += g2[c] * C2[t][c]   (b2 already in C2)
#pragma unroll
        for (int q = 0; q < 16; q++) {
            int i = q * 256 + tid;
            int cch = i >> 6, t = i & 63;
            float* pp = xp + (size_t)cch * 262144 + t;
            *pp = *pp + g2s[cch] * C2[t * 72 + cch];
        }
        __syncthreads();
    }
}

// ---------------------------------------------------------------------------
extern "C" void kernel_launch(void* const* d_in, const int* in_sizes, int n_in,
                              void* d_out, int out_size) {
    const float* x         = (const float*)d_in[0];
    const float* c         = (const float*)d_in[1];
    const float* sup_w     = (const float*)d_in[2];
    const float* sup_b     = (const float*)d_in[3];
    const float* qkv_w     = (const float*)d_in[4];
    const float* qkv_b     = (const float*)d_in[5];
    const float* out_w     = (const float*)d_in[6];
    const float* out_b     = (const float*)d_in[7];
    const float* recov_w   = (const float*)d_in[8];
    const float* recov_b   = (const float*)d_in[9];
    const float* ada_att_w = (const float*)d_in[10];
    const float* ada_att_b = (const float*)d_in[11];
    const float* ada_mlp_w = (const float*)d_in[12];
    const float* ada_mlp_b = (const float*)d_in[13];
    const float* fc1_w     = (const float*)d_in[14];
    const float* fc1_b     = (const float*)d_in[15];
    const float* fc2_w     = (const float*)d_in[16];
    const float* fc2_b     = (const float*)d_in[17];
    float* outp = (float*)d_out;

    cudaFuncSetAttribute(k_recov, cudaFuncAttributeMaxDynamicSharedMemorySize, 51200);
    cudaFuncSetAttribute(k_mlp,   cudaFuncAttributeMaxDynamicSharedMemorySize, MLPW_SMEM);

    float *p_xt, *p_qkv, *p_attn, *p_o, *p_attm;
    cudaGetSymbolAddress((void**)&p_xt,   g_xt);
    cudaGetSymbolAddress((void**)&p_qkv,  g_qkv);
    cudaGetSymbolAddress((void**)&p_attn, g_attn);
    cudaGetSymbolAddress((void**)&p_o,    g_o);
    cudaGetSymbolAddress((void**)&p_attm, g_attm);

    k_ada<<<240, 256>>>(c, ada_att_w, ada_att_b, ada_mlp_w, ada_mlp_b);
    k_ropetab<<<64, 256>>>();
    k_sup<<<dim3(8, 32, 2), 128>>>(x, sup_w, sup_b);
    k_ln_mod<<<dim3(32, 2), 256>>>();
    k_gemm64<<<dim3(12, 32), 256>>>(p_xt, qkv_w, qkv_b, p_qkv, 768, 256, nullptr, 1);
    k_attn2<<<dim3(8, 8, 4), 128>>>();
    k_attn_comb<<<512, 256>>>();
    k_gemm64<<<dim3(4, 32), 256>>>(p_attn, out_w, out_b, p_o, 256, 256, p_attm + 512, 0);
    k_upnorm<<<dim3(32, 2), 256>>>();
    k_recov<<<dim3(8, 32, 2), 128, 51200>>>(x, recov_w, recov_b, outp);
    k_mlp<<<dim3(16, 32, 2), 256, MLPW_SMEM>>>(outp, fc1_w, fc1_b, fc2_w, fc2_b);
}

// round 10
// speedup vs baseline: 4.1134x; 1.0515x over previous
#include <cuda_runtime.h>
#include <cuda_bf16.h>
#include <mma.h>
#include <math.h>

using namespace nvcuda;

// ---------------------------------------------------------------------------
// FullTimeAtt: B=2, C=64, F=256, T=1024, R=8, SUP=8, Fatt=32, D=256, H=8, hd=32
// fp32 f32x2 pipeline; MLP on WMMA bf16. R10: latency/occupancy fixes.
// ---------------------------------------------------------------------------

typedef unsigned long long u64t;

__device__ __forceinline__ u64t ffma2(u64t a, u64t b, u64t c) {
    u64t d;
    asm("fma.rn.f32x2 %0, %1, %2, %3;" : "=l"(d) : "l"(a), "l"(b), "l"(c));
    return d;
}
__device__ __forceinline__ u64t fmul2(u64t a, u64t b) {
    u64t d;
    asm("mul.rn.f32x2 %0, %1, %2;" : "=l"(d) : "l"(a), "l"(b));
    return d;
}
__device__ __forceinline__ u64t fpk(float lo, float hi) {
    u64t r;
    asm("mov.b64 %0, {%1, %2};" : "=l"(r) : "f"(lo), "f"(hi));
    return r;
}
__device__ __forceinline__ void fupk(u64t v, float& a, float& b) {
    asm("mov.b64 {%0, %1}, %2;" : "=f"(a), "=f"(b) : "l"(v));
}
__device__ __forceinline__ float fsum2(u64t v) {
    float a, b;
    fupk(v, a, b);
    return a + b;
}
__device__ __forceinline__ unsigned bfpack(float lo, float hi) {
    unsigned r;
    asm("cvt.rn.bf16x2.f32 %0, %1, %2;" : "=r"(r) : "f"(hi), "f"(lo));
    return r;
}

__device__ float g_attm[2 * 768];
__device__ float g_mlpm[2 * 192];
__device__ float g_cos[1024 * 16];
__device__ float g_sin[1024 * 16];
__device__ float g_xf  [2 * 256 * 1024];
__device__ float g_xt  [2 * 1024 * 256];
__device__ float g_qkv [2 * 1024 * 768];
__device__ float g_attn[2 * 1024 * 256];
__device__ float g_o   [2 * 1024 * 256];
__device__ float g_ln2 [2 * 256 * 1024];
__device__ float g_pacc[4 * 16384 * 32];   // 4-way split-kv partial acc
__device__ float g_pml [4 * 16384 * 2];    // 4-way split-kv partial (m,l)

// ---------------------------------------------------------------------------
// K0: adaLN matvecs (warps 0..1919) + fused RoPE tables (threads 61440..77823)
// ---------------------------------------------------------------------------
__global__ void k_ada(const float* __restrict__ c,
                      const float* __restrict__ aw, const float* __restrict__ ab,
                      const float* __restrict__ mw, const float* __restrict__ mb) {
    int gtid = blockIdx.x * 256 + threadIdx.x;
    int wid = gtid >> 5;
    int lane = threadIdx.x & 31;
    if (wid < 1920) {
        const float* w;
        const float* bia;
        float* dst;
        int b, o;
        if (wid < 1536) {
            b = wid / 768; o = wid % 768;
            w = aw + (size_t)o * 512; bia = ab; dst = g_attm + wid;
        } else {
            int i = wid - 1536;
            b = i / 192; o = i % 192;
            w = mw + (size_t)o * 512; bia = mb; dst = g_mlpm + i;
        }
        const float* cb = c + b * 512;
        float acc = 0.f;
        for (int k = lane; k < 512; k += 32) {
            float v = cb[k];
            float s = v / (1.f + __expf(-v));
            acc = fmaf(s, w[k], acc);
        }
#pragma unroll
        for (int off = 16; off; off >>= 1) acc += __shfl_xor_sync(0xffffffffu, acc, off);
        if (lane == 0) dst[0] = acc + bia[o];
    } else {
        int idx = gtid - 61440;
        if (idx < 16384) {
            int t = idx >> 4, j = idx & 15;
            float inv = (float)(1.0 / pow(10000.0, (double)(2 * j) / 32.0));
            float ang = (float)t * inv;
            float s, cc;
            sincosf(ang, &s, &cc);
            g_cos[idx] = cc;
            g_sin[idx] = s;
        }
    }
}

// ---------------------------------------------------------------------------
__global__ void k_sup(const float* __restrict__ x,
                      const float* __restrict__ sup_w,
                      const float* __restrict__ sup_b) {
    __shared__ __align__(16) float wt[512 * 16];
    __shared__ float bs[16];
    int tid = threadIdx.x;
    int b = blockIdx.z, fa = blockIdx.y;
    int t = blockIdx.x * 128 + tid;
    for (int i = tid; i < 512 * 16; i += 128) {
        int o = i >> 9, cr = i & 511;
        wt[cr * 16 + o] = sup_w[i];
    }
    if (tid < 16) bs[tid] = sup_b[tid];
    __syncthreads();

    const float* xb = x + ((size_t)(b * 64) * 256 + fa * 8) * 1024 + t;

    float s1[8], s2[8];
#pragma unroll
    for (int r = 0; r < 8; r++) { s1[r] = 0.f; s2[r] = 0.f; }
#pragma unroll 2
    for (int cch = 0; cch < 64; cch++) {
#pragma unroll
        for (int r = 0; r < 8; r++) {
            float v = xb[(size_t)(cch * 256 + r) * 1024];
            s1[r] += v;
            s2[r] = fmaf(v, v, s2[r]);
        }
    }
    float mu[8], rs[8];
#pragma unroll
    for (int r = 0; r < 8; r++) {
        mu[r] = s1[r] * (1.f / 64.f);
        float var = s2[r] * (1.f / 64.f) - mu[r] * mu[r];
        rs[r] = rsqrtf(var + 1e-6f);
    }

    u64t acc2[8];
#pragma unroll
    for (int q = 0; q < 8; q++) acc2[q] = 0ull;
#pragma unroll 2
    for (int cch = 0; cch < 64; cch++) {
#pragma unroll
        for (int r = 0; r < 8; r++) {
            float xn = (xb[(size_t)(cch * 256 + r) * 1024] - mu[r]) * rs[r];
            u64t x2 = fpk(xn, xn);
            const u64t* wp = (const u64t*)(wt + (cch * 8 + r) * 16);
#pragma unroll
            for (int q = 0; q < 8; q++) acc2[q] = ffma2(x2, wp[q], acc2[q]);
        }
    }
    float accv[16];
#pragma unroll
    for (int q = 0; q < 8; q++) fupk(acc2[q], accv[2 * q], accv[2 * q + 1]);
#pragma unroll
    for (int s = 0; s < 8; s++) {
        float ya = accv[s] + bs[s];
        float yb = accv[s + 8] + bs[s + 8];
        float outv = ya * (yb / (1.f + __expf(-yb)));
        g_xf[((size_t)(b * 256) + (s * 32 + fa)) * 1024 + t] = outv;
    }
}

// ---------------------------------------------------------------------------
// K2: LN over D=256 + modulate; 16-t tiles, grid (64, 2) = 128 blocks.
// ---------------------------------------------------------------------------
__global__ void k_ln_mod() {
    __shared__ __align__(16) float sm[256][17];
    __shared__ float shs[256], scs[256];
    __shared__ float red1[16][16], red2[16][16];
    __shared__ float smu[16], srs[16];
    int tid = threadIdx.x;  // 256
    int b = blockIdx.y;
    int t0 = blockIdx.x * 16;
    for (int i = tid; i < 256; i += 256) {
        shs[i] = g_attm[b * 768 + i];
        scs[i] = 1.f + g_attm[b * 768 + 256 + i];
    }
    for (int i = tid; i < 4096; i += 256) {
        int d = i >> 4, tt = i & 15;
        sm[d][tt] = g_xf[(size_t)(b * 256 + d) * 1024 + t0 + tt];
    }
    __syncthreads();
    int col = tid & 15, part = tid >> 4;
    float s1 = 0.f, s2 = 0.f;
#pragma unroll
    for (int j = 0; j < 16; j++) {
        float v = sm[part * 16 + j][col];
        s1 += v;
        s2 = fmaf(v, v, s2);
    }
    red1[part][col] = s1;
    red2[part][col] = s2;
    __syncthreads();
    if (tid < 16) {
        float a = 0.f, c2 = 0.f;
#pragma unroll
        for (int p = 0; p < 16; p++) { a += red1[p][tid]; c2 += red2[p][tid]; }
        float mu = a * (1.f / 256.f);
        smu[tid] = mu;
        srs[tid] = rsqrtf(c2 * (1.f / 256.f) - mu * mu + 1e-6f);
    }
    __syncthreads();
    for (int i = tid; i < 4096; i += 256) {
        int tt = i >> 8, d = i & 255;
        float v = (sm[d][tt] - smu[tt]) * srs[tt] * scs[d] + shs[d];
        g_xt[((size_t)(b * 1024) + t0 + tt) * 256 + d] = v;
    }
}

// ---------------------------------------------------------------------------
__global__ void k_gemm64(const float* __restrict__ A, const float* __restrict__ W,
                         const float* __restrict__ bias, float* __restrict__ C,
                         int N, int K, const float* __restrict__ gate, int rope) {
    __shared__ __align__(16) float As[64][17];
    __shared__ __align__(16) float Wst[16][66];
    int tid = threadIdx.x;
    int row0 = blockIdx.y * 64, col0 = blockIdx.x * 64;
    int ty = tid >> 4, tx = tid & 15;
    int lr = tid >> 2, lk = (tid & 3) * 4;
    u64t acc2[4][2];
#pragma unroll
    for (int i = 0; i < 4; i++) { acc2[i][0] = 0ull; acc2[i][1] = 0ull; }

    for (int k0 = 0; k0 < K; k0 += 16) {
        float4 av = *(const float4*)(A + (size_t)(row0 + lr) * K + k0 + lk);
        float4 wv = *(const float4*)(W + (size_t)(col0 + lr) * K + k0 + lk);
        __syncthreads();
        As[lr][lk + 0] = av.x; As[lr][lk + 1] = av.y; As[lr][lk + 2] = av.z; As[lr][lk + 3] = av.w;
        Wst[lk + 0][lr] = wv.x; Wst[lk + 1][lr] = wv.y; Wst[lk + 2][lr] = wv.z; Wst[lk + 3][lr] = wv.w;
        __syncthreads();
#pragma unroll
        for (int kk = 0; kk < 16; kk++) {
            const u64t* wr = (const u64t*)(&Wst[kk][0]);
            u64t b0 = wr[tx * 2], b1 = wr[tx * 2 + 1];
#pragma unroll
            for (int i = 0; i < 4; i++) {
                float a = As[ty * 4 + i][kk];
                u64t a2 = fpk(a, a);
                acc2[i][0] = ffma2(a2, b0, acc2[i][0]);
                acc2[i][1] = ffma2(a2, b1, acc2[i][1]);
            }
        }
    }
#pragma unroll
    for (int i = 0; i < 4; i++) {
        int r = row0 + ty * 4 + i;
        int t = r & 1023;
#pragma unroll
        for (int p = 0; p < 2; p++) {
            float v0, v1;
            fupk(acc2[i][p], v0, v1);
            int cc = col0 + tx * 4 + p * 2;
            v0 += bias[cc];
            v1 += bias[cc + 1];
            if (rope && cc < 512) {
                int j = (cc & 31) >> 1;
                float co = g_cos[t * 16 + j], si = g_sin[t * 16 + j];
                float r0 = v0 * co - v1 * si;
                float r1 = v0 * si + v1 * co;
                v0 = r0; v1 = r1;
            }
            if (gate) {
                v0 *= gate[(r >> 10) * 768 + cc];
                v1 *= gate[(r >> 10) * 768 + cc + 1];
            }
            float2 st; st.x = v0; st.y = v1;
            *(float2*)(C + (size_t)r * N + cc) = st;
        }
    }
}

// ---------------------------------------------------------------------------
// K4: split-KV (4-way) attention partials. block (qtile8, h8, b*4+sp), 128 thr.
// ---------------------------------------------------------------------------
__global__ void k_attn2() {
    __shared__ __align__(16) float ks[32][32];
    __shared__ __align__(16) float vs[32][32];
    int tid = threadIdx.x;
    int z = blockIdx.z;
    int b = z >> 2, sp = z & 3;
    int h = blockIdx.y;
    int t = blockIdx.x * 128 + tid;
    const float* qp = g_qkv + ((size_t)(b * 1024) + t) * 768 + h * 32;
    u64t q2[16];
    const u64t* qq = (const u64t*)qp;
#pragma unroll
    for (int i = 0; i < 16; i++) q2[i] = qq[i];
    float m = -1e30f, l = 0.f;
    u64t acc2[16];
#pragma unroll
    for (int i = 0; i < 16; i++) acc2[i] = 0ull;
    const float scale = 0.17677669529663689f;

    int s_begin = sp * 256;
    for (int st0 = s_begin; st0 < s_begin + 256; st0 += 32) {
        __syncthreads();
        for (int i = tid; i < 256; i += 128) {
            int rr = i >> 3, c4 = (i & 7) * 4;
            const float* kb = g_qkv + ((size_t)(b * 1024) + st0 + rr) * 768 + 256 + h * 32 + c4;
            *(float4*)(&ks[rr][c4]) = *(const float4*)kb;
            *(float4*)(&vs[rr][c4]) = *(const float4*)(kb + 256);
        }
        __syncthreads();
        float scl[32];
        float tmax = -1e30f;
#pragma unroll
        for (int s = 0; s < 32; s++) {
            const u64t* kr = (const u64t*)(&ks[s][0]);
            u64t da = 0ull, db = 0ull;
#pragma unroll
            for (int q = 0; q < 16; q += 2) {
                da = ffma2(q2[q], kr[q], da);
                db = ffma2(q2[q + 1], kr[q + 1], db);
            }
            float dot = (fsum2(da) + fsum2(db)) * scale;
            scl[s] = dot;
            tmax = fmaxf(tmax, dot);
        }
        float mn = fmaxf(m, tmax);
        float corr = __expf(m - mn);
        l *= corr;
        u64t c2 = fpk(corr, corr);
#pragma unroll
        for (int i = 0; i < 16; i++) acc2[i] = fmul2(acc2[i], c2);
#pragma unroll
        for (int s = 0; s < 32; s++) {
            float p = __expf(scl[s] - mn);
            l += p;
            u64t p2 = fpk(p, p);
            const u64t* vr = (const u64t*)(&vs[s][0]);
#pragma unroll
            for (int i = 0; i < 16; i++) acc2[i] = ffma2(p2, vr[i], acc2[i]);
        }
        m = mn;
    }
    int r0 = sp * 16384 + (b * 8 + h) * 1024 + t;
    g_pml[r0 * 2] = m;
    g_pml[r0 * 2 + 1] = l;
    float* op = g_pacc + (size_t)r0 * 32;
#pragma unroll
    for (int i = 0; i < 16; i += 2) {
        float4 o;
        fupk(acc2[i], o.x, o.y);
        fupk(acc2[i + 1], o.z, o.w);
        *(float4*)(op + 2 * i) = o;
    }
}

// ---------------------------------------------------------------------------
// K4b: combine 4 split-KV partials -> g_attn[b][t][h*32+d]
// ---------------------------------------------------------------------------
__global__ void k_attn_comb() {
    int idx = blockIdx.x * 256 + threadIdx.x;   // 131072
    int row = idx >> 3, q4 = idx & 7;
    int b = row >> 13, rem = row & 8191;
    int h = rem >> 10, t = rem & 1023;
    int r0 = (b * 8 + h) * 1024 + t;
    float mv[4], lv[4];
#pragma unroll
    for (int sp = 0; sp < 4; sp++) {
        mv[sp] = g_pml[(sp * 16384 + r0) * 2];
        lv[sp] = g_pml[(sp * 16384 + r0) * 2 + 1];
    }
    float mM = fmaxf(fmaxf(mv[0], mv[1]), fmaxf(mv[2], mv[3]));
    float e[4], L = 0.f;
#pragma unroll
    for (int sp = 0; sp < 4; sp++) {
        e[sp] = __expf(mv[sp] - mM);
        L += lv[sp] * e[sp];
    }
    float inv = 1.f / L;
    float4 o = {0.f, 0.f, 0.f, 0.f};
#pragma unroll
    for (int sp = 0; sp < 4; sp++) {
        float4 a = ((const float4*)g_pacc)[(size_t)(sp * 16384 + r0) * 8 + q4];
        float w = e[sp] * inv;
        o.x = fmaf(a.x, w, o.x);
        o.y = fmaf(a.y, w, o.y);
        o.z = fmaf(a.z, w, o.z);
        o.w = fmaf(a.w, w, o.w);
    }
    ((float4*)g_attn)[(((size_t)(b * 1024) + t) * 256 + h * 32) / 4 + q4] = o;
}

// ---------------------------------------------------------------------------
// K5b: up_norm; 16-t tiles, grid (64, 2) = 128 blocks.
// ---------------------------------------------------------------------------
__global__ void k_upnorm() {
    __shared__ __align__(16) float sm[256][17];
    __shared__ float red1[16][16], red2[16][16];
    __shared__ float smu[16], srs[16];
    int tid = threadIdx.x;  // 256
    int b = blockIdx.y;
    int t0 = blockIdx.x * 16;
    for (int i = tid; i < 4096; i += 256) {
        int tt = i >> 8, d = i & 255;
        sm[d][tt] = g_o[((size_t)(b * 1024) + t0 + tt) * 256 + d];
    }
    __syncthreads();
    int col = tid & 15, part = tid >> 4;
    float s1 = 0.f, s2 = 0.f;
#pragma unroll
    for (int j = 0; j < 16; j++) {
        float v = sm[part * 16 + j][col];
        s1 += v;
        s2 = fmaf(v, v, s2);
    }
    red1[part][col] = s1;
    red2[part][col] = s2;
    __syncthreads();
    if (tid < 16) {
        float a = 0.f, c2 = 0.f;
#pragma unroll
        for (int p = 0; p < 16; p++) { a += red1[p][tid]; c2 += red2[p][tid]; }
        float mu = a * (1.f / 256.f);
        smu[tid] = mu;
        srs[tid] = rsqrtf(c2 * (1.f / 256.f) - mu * mu + 1e-6f);
    }
    __syncthreads();
    for (int i = tid; i < 4096; i += 256) {
        int d = i >> 4, tt = i & 15;
        g_ln2[(size_t)(b * 256 + d) * 1024 + t0 + tt] = (sm[d][tt] - smu[tt]) * srs[tt];
    }
}

// ---------------------------------------------------------------------------
// K6: recov conv(3,1) + pixel-shuffle + residual. 256 thr: o-range split.
// ---------------------------------------------------------------------------
__global__ void k_recov(const float* __restrict__ x,
                        const float* __restrict__ rw,
                        const float* __restrict__ rb,
                        float* __restrict__ outp) {
    extern __shared__ float sm6[];
    float* ws = sm6;
    float* bbs = sm6 + 512 * 24;
    int tid = threadIdx.x;  // 256
    int b = blockIdx.z, fa = blockIdx.y;
    int t = blockIdx.x * 128 + (tid & 127);
    int o0 = (tid >> 7) * 256;
    for (int i = tid; i < 3072; i += 256) ((float4*)ws)[i] = ((const float4*)rw)[i];
    for (int i = tid; i < 512; i += 256) bbs[i] = rb[i];
    __syncthreads();

    float xv[24];
#pragma unroll
    for (int i = 0; i < 8; i++) {
#pragma unroll
        for (int kh = 0; kh < 3; kh++) {
            int fs = fa + kh - 1;
            xv[i * 3 + kh] = (fs >= 0 && fs < 32)
                ? g_ln2[((size_t)(b * 256) + i * 32 + fs) * 1024 + t] : 0.f;
        }
    }
    u64t xv2[12];
#pragma unroll
    for (int q = 0; q < 12; q++) xv2[q] = fpk(xv[2 * q], xv[2 * q + 1]);

#pragma unroll 2
    for (int o = o0; o < o0 + 256; o++) {
        const u64t* wp = (const u64t*)(ws + o * 24);
        u64t aa = 0ull, bb2 = 0ull;
#pragma unroll
        for (int q = 0; q < 12; q += 2) {
            aa = ffma2(xv2[q], wp[q], aa);
            bb2 = ffma2(xv2[q + 1], wp[q + 1], bb2);
        }
        float accv = fsum2(aa) + fsum2(bb2) + bbs[o];
        int cch = o >> 3, r = o & 7;
        size_t idx = ((size_t)(b * 64 + cch) * 256 + fa * 8 + r) * 1024 + t;
        outp[idx] = x[idx] + accv;
    }
}

// ---------------------------------------------------------------------------
// K7: gated MLP via WMMA bf16. Grid (16 ttile, 16 fg, 2 b), 256 thr, 16 f-iters.
// R10: xs kept live for epilogue residual (no global re-read);
//      register prefetch of next f-tile issued before GEMM1.
// ---------------------------------------------------------------------------
#define W1BF_OFF  0u        // bf16 [256][72]  = 36864
#define W2BF_OFF  36864u    // bf16 [64][136]  = 17408
#define BREP_OFF  54272u    // f32 [16][264]   = 16896
#define B2REP_OFF 71168u    // f32 [16][72]    = 4608
#define ABF_OFF   75776u    // bf16 [64][72]   = 9216
#define XS_OFF    84992u    // f32 [64][72]    = 18432
#define HF_OFF    103424u   // f32 [64][136]   = 34816
#define HBF_OFF   138240u   // bf16 [64][136]  = 17408
#define C2_OFF    155648u   // f32 [64][72]    = 18432
#define G2_OFF    174080u
#define SH2_OFF   174336u
#define SC2_OFF   174592u
#define SMU_OFF   174848u
#define SRS_OFF   175104u
#define MLPW_SMEM 175360

__global__ void __launch_bounds__(256)
k_mlp(float* __restrict__ xio,
      const float* __restrict__ fc1w, const float* __restrict__ fc1b,
      const float* __restrict__ fc2w, const float* __restrict__ fc2b) {
    extern __shared__ __align__(16) unsigned char smw[];
    __nv_bfloat16* W1bf = (__nv_bfloat16*)(smw + W1BF_OFF);
    __nv_bfloat16* W2bf = (__nv_bfloat16*)(smw + W2BF_OFF);
    float* brep  = (float*)(smw + BREP_OFF);
    float* b2rep = (float*)(smw + B2REP_OFF);
    __nv_bfloat16* Abf = (__nv_bfloat16*)(smw + ABF_OFF);
    float* xs = (float*)(smw + XS_OFF);
    float* Hf = (float*)(smw + HF_OFF);
    __nv_bfloat16* Hbf = (__nv_bfloat16*)(smw + HBF_OFF);
    float* C2  = (float*)(smw + C2_OFF);
    float* g2s = (float*)(smw + G2_OFF);
    float* sh2 = (float*)(smw + SH2_OFF);
    float* sc2 = (float*)(smw + SC2_OFF);
    float* smu = (float*)(smw + SMU_OFF);
    float* srs = (float*)(smw + SRS_OFF);

    int tid = threadIdx.x;
    int wid = tid >> 5;
    int b = blockIdx.z, fg = blockIdx.y;
    int t0 = blockIdx.x * 64;
    int fbase = fg * 16;

    unsigned* W1u = (unsigned*)W1bf;
    for (int i = tid; i < 8192; i += 256) {
        int o = i >> 5, p = i & 31;
        W1u[o * 36 + p] = bfpack(fc1w[o * 64 + 2 * p], fc1w[o * 64 + 2 * p + 1]);
    }
    unsigned* W2u = (unsigned*)W2bf;
    for (int i = tid; i < 4096; i += 256) {
        int o = i >> 6, p = i & 63;
        W2u[o * 68 + p] = bfpack(fc2w[o * 128 + 2 * p], fc2w[o * 128 + 2 * p + 1]);
    }
    for (int i = tid; i < 4096; i += 256) {
        int r = i >> 8, cc = i & 255;
        brep[r * 264 + cc] = fc1b[cc];
    }
    for (int i = tid; i < 1024; i += 256) {
        int r = i >> 6, cc = i & 63;
        b2rep[r * 72 + cc] = fc2b[cc];
    }
    if (tid < 64) {
        sh2[tid] = g_mlpm[b * 192 + tid];
        sc2[tid] = g_mlpm[b * 192 + 64 + tid];
        g2s[tid] = g_mlpm[b * 192 + 128 + tid];
    }

    // prefetch the first f-tile while weights load
    float pre[16];
    {
        float* xp0 = xio + ((size_t)(b * 64) * 256 + fbase) * 1024 + t0;
#pragma unroll
        for (int q = 0; q < 16; q++) {
            int i = q * 256 + tid;
            int cch = i >> 6, t = i & 63;
            pre[q] = xp0[(size_t)cch * 262144 + t];
        }
    }
    __syncthreads();

    for (int fi = 0; fi < 16; fi++) {
        int f = fbase + fi;
        float* xp = xio + ((size_t)(b * 64) * 256 + f) * 1024 + t0;

        // 1. commit prefetched tile to xs[t][c] (ld 72)
#pragma unroll
        for (int q = 0; q < 16; q++) {
            int i = q * 256 + tid;
            int cch = i >> 6, t = i & 63;
            xs[t * 72 + cch] = pre[q];
        }
        __syncthreads();

        // 2. per-position LN stats: 4 threads / position
        {
            int pos = tid >> 2, quad = tid & 3;
            const float* row = xs + pos * 72 + quad * 16;
            float s1 = 0.f, s2 = 0.f;
#pragma unroll
            for (int cch = 0; cch < 16; cch++) {
                float v = row[cch];
                s1 += v;
                s2 = fmaf(v, v, s2);
            }
            s1 += __shfl_xor_sync(0xffffffffu, s1, 1);
            s2 += __shfl_xor_sync(0xffffffffu, s2, 1);
            s1 += __shfl_xor_sync(0xffffffffu, s1, 2);
            s2 += __shfl_xor_sync(0xffffffffu, s2, 2);
            if (quad == 0) {
                float mu = s1 * (1.f / 64.f);
                smu[pos] = mu;
                srs[pos] = rsqrtf(s2 * (1.f / 64.f) - mu * mu + 1e-6f);
            }
        }
        __syncthreads();

        // 3. normalize + modulate -> Abf
        {
            unsigned* Au = (unsigned*)Abf;
#pragma unroll
            for (int q = 0; q < 8; q++) {
                int i = q * 256 + tid;
                int pos = i >> 5, p = i & 31;
                float mu = smu[pos], rs = srs[pos];
                float a0 = (xs[pos * 72 + 2 * p]     - mu) * rs * (1.f + sc2[2 * p])     + sh2[2 * p];
                float a1 = (xs[pos * 72 + 2 * p + 1] - mu) * rs * (1.f + sc2[2 * p + 1]) + sh2[2 * p + 1];
                Au[pos * 36 + p] = bfpack(a0, a1);
            }
        }
        __syncthreads();

        // prefetch next f-tile (hidden under GEMM phases)
        if (fi + 1 < 16) {
            float* xpn = xp + 1024;
#pragma unroll
            for (int q = 0; q < 16; q++) {
                int i = q * 256 + tid;
                int cch = i >> 6, t = i & 63;
                pre[q] = xpn[(size_t)cch * 262144 + t];
            }
        }

        // 4. GEMM1 + fragment GLU -> Hf
        {
            wmma::fragment<wmma::matrix_a, 16, 16, 16, __nv_bfloat16, wmma::row_major> afr;
            wmma::fragment<wmma::matrix_b, 16, 16, 16, __nv_bfloat16, wmma::col_major> bu, bg;
            wmma::fragment<wmma::accumulator, 16, 16, 16, float> cu, cg;
            int m0 = (wid >> 1) * 16;
#pragma unroll
            for (int j = 0; j < 4; j++) {
                int nU = ((wid & 1) * 4 + j) * 16;
                wmma::load_matrix_sync(cu, brep + nU, 264, wmma::mem_row_major);
                wmma::load_matrix_sync(cg, brep + 128 + nU, 264, wmma::mem_row_major);
#pragma unroll
                for (int k = 0; k < 4; k++) {
                    wmma::load_matrix_sync(afr, Abf + m0 * 72 + k * 16, 72);
                    wmma::load_matrix_sync(bu, W1bf + nU * 72 + k * 16, 72);
                    wmma::load_matrix_sync(bg, W1bf + (size_t)(128 + nU) * 72 + k * 16, 72);
                    wmma::mma_sync(cu, afr, bu, cu);
                    wmma::mma_sync(cg, afr, bg, cg);
                }
#pragma unroll
                for (int e = 0; e < cu.num_elements; e++) {
                    float g = cg.x[e];
                    cu.x[e] = cu.x[e] * __fdividef(g, 1.f + __expf(-g));
                }
                wmma::store_matrix_sync(Hf + m0 * 136 + nU, cu, 136, wmma::mem_row_major);
            }
        }
        __syncthreads();

        // 5. pack Hf -> Hbf
        {
            unsigned* Hu = (unsigned*)Hbf;
#pragma unroll
            for (int q = 0; q < 16; q++) {
                int i = q * 256 + tid;
                int pos = i >> 6, p = i & 63;
                Hu[pos * 68 + p] = bfpack(Hf[pos * 136 + 2 * p], Hf[pos * 136 + 2 * p + 1]);
            }
        }
        __syncthreads();

        // 6. GEMM2 -> C2 (bias2 via acc init)
        {
            wmma::fragment<wmma::matrix_a, 16, 16, 16, __nv_bfloat16, wmma::row_major> afr;
            wmma::fragment<wmma::matrix_b, 16, 16, 16, __nv_bfloat16, wmma::col_major> bfr;
            wmma::fragment<wmma::accumulator, 16, 16, 16, float> acc;
#pragma unroll
            for (int s = 0; s < 2; s++) {
                int idx = wid * 2 + s;
                int m0 = (idx >> 2) * 16, n0 = (idx & 3) * 16;
                wmma::load_matrix_sync(acc, b2rep + n0, 72, wmma::mem_row_major);
#pragma unroll
                for (int k = 0; k < 8; k++) {
                    wmma::load_matrix_sync(afr, Hbf + m0 * 136 + k * 16, 136);
                    wmma::load_matrix_sync(bfr, W2bf + n0 * 136 + k * 16, 136);
                    wmma::mma_sync(acc, afr, bfr, acc);
                }
                wmma::store_matrix_sync(C2 + m0 * 72 + n0, acc, 72, wmma::mem_row_major);
            }
        }
        __syncthreads();

        // 7. epilogue: out = xs + g2[c]*C2  (residual from smem — STG only)
#pragma unroll
        for (int q = 0; q < 16; q++) {
            int i = q * 256 + tid;
            int cch = i >> 6, t = i & 63;
            xp[(size_t)cch * 262144 + t] = xs[t * 72 + cch] + g2s[cch] * C2[t * 72 + cch];
        }
        __syncthreads();
    }
}

// ---------------------------------------------------------------------------
extern "C" void kernel_launch(void* const* d_in, const int* in_sizes, int n_in,
                              void* d_out, int out_size) {
    const float* x         = (const float*)d_in[0];
    const float* c         = (const float*)d_in[1];
    const float* sup_w     = (const float*)d_in[2];
    const float* sup_b     = (const float*)d_in[3];
    const float* qkv_w     = (const float*)d_in[4];
    const float* qkv_b     = (const float*)d_in[5];
    const float* out_w     = (const float*)d_in[6];
    const float* out_b     = (const float*)d_in[7];
    const float* recov_w   = (const float*)d_in[8];
    const float* recov_b   = (const float*)d_in[9];
    const float* ada_att_w = (const float*)d_in[10];
    const float* ada_att_b = (const float*)d_in[11];
    const float* ada_mlp_w = (const float*)d_in[12];
    const float* ada_mlp_b = (const float*)d_in[13];
    const float* fc1_w     = (const float*)d_in[14];
    const float* fc1_b     = (const float*)d_in[15];
    const float* fc2_w     = (const float*)d_in[16];
    const float* fc2_b     = (const float*)d_in[17];
    float* outp = (float*)d_out;

    cudaFuncSetAttribute(k_recov, cudaFuncAttributeMaxDynamicSharedMemorySize, 51200);
    cudaFuncSetAttribute(k_mlp,   cudaFuncAttributeMaxDynamicSharedMemorySize, MLPW_SMEM);

    float *p_xt, *p_qkv, *p_attn, *p_o, *p_attm;
    cudaGetSymbolAddress((void**)&p_xt,   g_xt);
    cudaGetSymbolAddress((void**)&p_qkv,  g_qkv);
    cudaGetSymbolAddress((void**)&p_attn, g_attn);
    cudaGetSymbolAddress((void**)&p_o,    g_o);
    cudaGetSymbolAddress((void**)&p_attm, g_attm);

    k_ada<<<304, 256>>>(c, ada_att_w, ada_att_b, ada_mlp_w, ada_mlp_b);
    k_sup<<<dim3(8, 32, 2), 128>>>(x, sup_w, sup_b);
    k_ln_mod<<<dim3(64, 2), 256>>>();
    k_gemm64<<<dim3(12, 32), 256>>>(p_xt, qkv_w, qkv_b, p_qkv, 768, 256, nullptr, 1);
    k_attn2<<<dim3(8, 8, 8), 128>>>();
    k_attn_comb<<<512, 256>>>();
    k_gemm64<<<dim3(4, 32), 256>>>(p_attn, out_w, out_b, p_o, 256, 256, p_attm + 512, 0);
    k_upnorm<<<dim3(64, 2), 256>>>();
    k_recov<<<dim3(8, 32, 2), 256, 51200>>>(x, recov_w, recov_b, outp);
    k_mlp<<<dim3(16, 16, 2), 256, MLPW_SMEM>>>(outp, fc1_w, fc1_b, fc2_w, fc2_b);
}